// round 6
// baseline (speedup 1.0000x reference)
#include <cuda_runtime.h>
#include <cuda_bf16.h>
#include <math.h>

#define N_MAX 100000
#define E_MAX 1600000
#define F0 256
#define F1 128
#define F2 16

// ---------------- scratch (static device globals; no allocation) ------------
__device__ int   g_deg[N_MAX];
__device__ float g_dinv[N_MAX];
__device__ int   g_rowptr[N_MAX + 1];
__device__ int   g_cursor[N_MAX];
__device__ int   g_csr[E_MAX];
__device__ float g_h1[(size_t)N_MAX * F1];   // scaled h1 = (x@W1) * dinv[row]
__device__ float g_h2[(size_t)N_MAX * F2];   // scaled h2 = (relu(agg1)@W2)*dinv
__device__ int   g_bsums[64];

// ---------------- packed f32x2 helpers (sm_103a) -----------------------------
__device__ __forceinline__ void ffma2(unsigned long long& d,
                                      unsigned long long a,
                                      unsigned long long b) {
    asm("fma.rn.f32x2 %0, %1, %2, %0;" : "+l"(d) : "l"(a), "l"(b));
}
__device__ __forceinline__ void unpack2(float& lo, float& hi, unsigned long long v) {
    asm("mov.b64 {%0, %1}, %2;" : "=f"(lo), "=f"(hi) : "l"(v));
}

// ---------------- zero init --------------------------------------------------
__global__ void k_zero(int n) {
    int i = blockIdx.x * blockDim.x + threadIdx.x;
    if (i < n) g_deg[i] = 0;
}

// ---------------- degree histogram (edge_index is int32) ---------------------
__global__ void k_deg(const int* __restrict__ ei, int E, int n) {
    int i = blockIdx.x * blockDim.x + threadIdx.x;
    if (i < E) {
        int dst = ei[E + i];
        if ((unsigned)dst < (unsigned)n) atomicAdd(&g_deg[dst], 1);
    }
}

__global__ void k_dinv(int n) {
    int i = blockIdx.x * blockDim.x + threadIdx.x;
    if (i < n) g_dinv[i] = rsqrtf((float)(g_deg[i] + 1));  // +1 self loop
}

// ---------------- 3-phase exclusive scan (4096 elems / block) ---------------
__global__ void k_scan1(int n) {
    __shared__ int warpsum[8];
    int base = blockIdx.x * 4096;
    int t0 = base + threadIdx.x * 16;
    int vals[16];
    int s = 0;
#pragma unroll
    for (int j = 0; j < 16; j++) {
        int idx = t0 + j;
        int v = (idx < n) ? g_deg[idx] : 0;
        vals[j] = s;
        s += v;
    }
    int lane = threadIdx.x & 31, w = threadIdx.x >> 5;
    int x = s;
#pragma unroll
    for (int d = 1; d < 32; d <<= 1) {
        int y = __shfl_up_sync(0xffffffffu, x, d);
        if (lane >= d) x += y;
    }
    if (lane == 31) warpsum[w] = x;
    __syncthreads();
    if (w == 0 && lane < 8) {
        int y = warpsum[lane];
#pragma unroll
        for (int d = 1; d < 8; d <<= 1) {
            int z = __shfl_up_sync(0xffu, y, d);
            if (lane >= d) y += z;
        }
        warpsum[lane] = y;
    }
    __syncthreads();
    int warpoff = (w > 0) ? warpsum[w - 1] : 0;
    int throff = warpoff + x - s;
#pragma unroll
    for (int j = 0; j < 16; j++) {
        int idx = t0 + j;
        if (idx < n) g_rowptr[idx] = throff + vals[j];
    }
    if (threadIdx.x == 255) g_bsums[blockIdx.x] = warpoff + x;
}

__global__ void k_scan2(int nb) {
    if (threadIdx.x == 0 && blockIdx.x == 0) {
        int s = 0;
        for (int i = 0; i < nb; i++) { int v = g_bsums[i]; g_bsums[i] = s; s += v; }
    }
}

__global__ void k_scan3(int n, int E) {
    int i = blockIdx.x * blockDim.x + threadIdx.x;
    if (i < n) {
        int r = g_rowptr[i] + g_bsums[i >> 12];
        g_rowptr[i] = r;
        g_cursor[i] = r;
    }
    if (i == 0) g_rowptr[n] = E;
}

// ---------------- CSR fill ---------------------------------------------------
__global__ void k_fill(const int* __restrict__ ei, int E, int n) {
    int i = blockIdx.x * blockDim.x + threadIdx.x;
    if (i < E) {
        int dst = ei[E + i];
        int src = ei[i];
        if ((unsigned)dst < (unsigned)n && (unsigned)src < (unsigned)n) {
            int pos = atomicAdd(&g_cursor[dst], 1);
            g_csr[pos] = src;
        }
    }
}

// ---------------- GEMM1: [M,256]x[256,128], FFMA2 (f32x2) path ---------------
// 128x128x16 double-buffered, 256 threads, 8x8 tile packed as 4x8 f32x2 pairs.
// A pairs come free from float4 LDS (pairs along M); B stored DUPLICATED in
// smem so b-dup pairs also come free from LDS.128 -> 32 FFMA2 + 6 LDS per k.
__global__ void __launch_bounds__(256) k_gemm1(
    const float* __restrict__ X, const float* __restrict__ W, int M) {
    __shared__ float As[2][16][128];
    __shared__ float Bs[2][16][256];   // duplicated pairs: Bs[k][2c]=Bs[k][2c+1]=W[k][c]
    int tid = threadIdx.x;
    int tx = tid & 15;           // col tile *8
    int ty = tid >> 4;           // row tile *8
    int m0 = blockIdx.x * 128;

    int arow = tid >> 2;         // 0..63 (and +64)
    int ac4  = (tid & 3) * 4;    // 0,4,8,12
    int brow = tid >> 5;         // 0..7  (and +8)
    int bc4  = (tid & 31) * 4;   // 0..124

    unsigned long long acc2[4][8];
#pragma unroll
    for (int p = 0; p < 4; p++)
#pragma unroll
        for (int j = 0; j < 8; j++) acc2[p][j] = 0ULL;  // {+0.f,+0.f}

    const float4 z4 = make_float4(0.f, 0.f, 0.f, 0.f);
    union U { float4 f; unsigned long long u[2]; };

    // preload tile 0
    {
        int gm0 = m0 + arow, gm1 = m0 + arow + 64;
        float4 va0 = (gm0 < M) ? *(const float4*)(X + (size_t)gm0 * F0 + ac4) : z4;
        float4 va1 = (gm1 < M) ? *(const float4*)(X + (size_t)gm1 * F0 + ac4) : z4;
        As[0][ac4 + 0][arow]      = va0.x;
        As[0][ac4 + 1][arow]      = va0.y;
        As[0][ac4 + 2][arow]      = va0.z;
        As[0][ac4 + 3][arow]      = va0.w;
        As[0][ac4 + 0][arow + 64] = va1.x;
        As[0][ac4 + 1][arow + 64] = va1.y;
        As[0][ac4 + 2][arow + 64] = va1.z;
        As[0][ac4 + 3][arow + 64] = va1.w;
        float4 vb0 = *(const float4*)(W + (size_t)brow * F1 + bc4);
        float4 vb1 = *(const float4*)(W + (size_t)(brow + 8) * F1 + bc4);
        *(float4*)(&Bs[0][brow][2 * bc4])         = make_float4(vb0.x, vb0.x, vb0.y, vb0.y);
        *(float4*)(&Bs[0][brow][2 * bc4 + 4])     = make_float4(vb0.z, vb0.z, vb0.w, vb0.w);
        *(float4*)(&Bs[0][brow + 8][2 * bc4])     = make_float4(vb1.x, vb1.x, vb1.y, vb1.y);
        *(float4*)(&Bs[0][brow + 8][2 * bc4 + 4]) = make_float4(vb1.z, vb1.z, vb1.w, vb1.w);
    }
    __syncthreads();

#pragma unroll 1
    for (int it = 0; it < 16; it++) {
        int cur = it & 1, nxt = cur ^ 1;
        float4 pa0, pa1, pb0, pb1;
        if (it < 15) {
            int k0 = (it + 1) * 16;
            int gm0 = m0 + arow, gm1 = m0 + arow + 64;
            pa0 = (gm0 < M) ? *(const float4*)(X + (size_t)gm0 * F0 + k0 + ac4) : z4;
            pa1 = (gm1 < M) ? *(const float4*)(X + (size_t)gm1 * F0 + k0 + ac4) : z4;
            pb0 = *(const float4*)(W + (size_t)(k0 + brow) * F1 + bc4);
            pb1 = *(const float4*)(W + (size_t)(k0 + brow + 8) * F1 + bc4);
        }
#pragma unroll
        for (int k = 0; k < 16; k++) {
            U a0, a1, b0, b1, b2, b3;
            a0.f = *(const float4*)(&As[cur][k][ty * 8]);
            a1.f = *(const float4*)(&As[cur][k][ty * 8 + 4]);
            b0.f = *(const float4*)(&Bs[cur][k][tx * 16]);
            b1.f = *(const float4*)(&Bs[cur][k][tx * 16 + 4]);
            b2.f = *(const float4*)(&Bs[cur][k][tx * 16 + 8]);
            b3.f = *(const float4*)(&Bs[cur][k][tx * 16 + 12]);
            unsigned long long ap[4] = {a0.u[0], a0.u[1], a1.u[0], a1.u[1]};
            unsigned long long bd[8] = {b0.u[0], b0.u[1], b1.u[0], b1.u[1],
                                        b2.u[0], b2.u[1], b3.u[0], b3.u[1]};
#pragma unroll
            for (int p = 0; p < 4; p++)
#pragma unroll
                for (int j = 0; j < 8; j++) ffma2(acc2[p][j], ap[p], bd[j]);
        }
        if (it < 15) {
            As[nxt][ac4 + 0][arow]      = pa0.x;
            As[nxt][ac4 + 1][arow]      = pa0.y;
            As[nxt][ac4 + 2][arow]      = pa0.z;
            As[nxt][ac4 + 3][arow]      = pa0.w;
            As[nxt][ac4 + 0][arow + 64] = pa1.x;
            As[nxt][ac4 + 1][arow + 64] = pa1.y;
            As[nxt][ac4 + 2][arow + 64] = pa1.z;
            As[nxt][ac4 + 3][arow + 64] = pa1.w;
            *(float4*)(&Bs[nxt][brow][2 * bc4])         = make_float4(pb0.x, pb0.x, pb0.y, pb0.y);
            *(float4*)(&Bs[nxt][brow][2 * bc4 + 4])     = make_float4(pb0.z, pb0.z, pb0.w, pb0.w);
            *(float4*)(&Bs[nxt][brow + 8][2 * bc4])     = make_float4(pb1.x, pb1.x, pb1.y, pb1.y);
            *(float4*)(&Bs[nxt][brow + 8][2 * bc4 + 4]) = make_float4(pb1.z, pb1.z, pb1.w, pb1.w);
        }
        __syncthreads();
    }

    // epilogue: pair p covers rows ty*8 + 2p (lo) and +2p+1 (hi)
#pragma unroll
    for (int p = 0; p < 4; p++) {
        float lo[8], hi[8];
#pragma unroll
        for (int j = 0; j < 8; j++) unpack2(lo[j], hi[j], acc2[p][j]);
        int r0 = m0 + ty * 8 + 2 * p;
        int r1 = r0 + 1;
        if (r0 < M) {
            float s = g_dinv[r0];
            *(float4*)(g_h1 + (size_t)r0 * F1 + tx * 8) =
                make_float4(lo[0] * s, lo[1] * s, lo[2] * s, lo[3] * s);
            *(float4*)(g_h1 + (size_t)r0 * F1 + tx * 8 + 4) =
                make_float4(lo[4] * s, lo[5] * s, lo[6] * s, lo[7] * s);
        }
        if (r1 < M) {
            float s = g_dinv[r1];
            *(float4*)(g_h1 + (size_t)r1 * F1 + tx * 8) =
                make_float4(hi[0] * s, hi[1] * s, hi[2] * s, hi[3] * s);
            *(float4*)(g_h1 + (size_t)r1 * F1 + tx * 8 + 4) =
                make_float4(hi[4] * s, hi[5] * s, hi[6] * s, hi[7] * s);
        }
    }
}

// ---------------- Agg1 + fused GEMM2 ----------------------------------------
__global__ void __launch_bounds__(256) k_agg1(
    const float* __restrict__ b1, const float* __restrict__ W2, int n) {
    __shared__ float Wt[F2][F1];   // transposed: Wt[q][k] = W2[k][q]
    for (int idx = threadIdx.x; idx < (F1 * F2) / 4; idx += 256) {
        int k = idx >> 2;
        int q4 = (idx & 3) * 4;
        float4 v = *(const float4*)(W2 + (size_t)k * F2 + q4);
        Wt[q4 + 0][k] = v.x;
        Wt[q4 + 1][k] = v.y;
        Wt[q4 + 2][k] = v.z;
        Wt[q4 + 3][k] = v.w;
    }
    __syncthreads();

    int warp = (blockIdx.x * blockDim.x + threadIdx.x) >> 5;
    int lane = threadIdx.x & 31;
    if (warp >= n) return;
    int i = warp;
    int beg = g_rowptr[i], end = g_rowptr[i + 1];
    const float* hs = g_h1;
    float4 acc0 = *(const float4*)(hs + (size_t)i * F1 + lane * 4);  // self loop
    float4 acc1 = make_float4(0.f, 0.f, 0.f, 0.f);
    for (int e = beg; e < end; e += 32) {
        int cnt = min(32, end - e);
        int j = (e + lane < end) ? g_csr[e + lane] : 0;
        int t = 0;
        for (; t + 1 < cnt; t += 2) {
            int j0 = __shfl_sync(0xffffffffu, j, t);
            int j1 = __shfl_sync(0xffffffffu, j, t + 1);
            float4 v0 = *(const float4*)(hs + (size_t)j0 * F1 + lane * 4);
            float4 v1 = *(const float4*)(hs + (size_t)j1 * F1 + lane * 4);
            acc0.x += v0.x; acc0.y += v0.y; acc0.z += v0.z; acc0.w += v0.w;
            acc1.x += v1.x; acc1.y += v1.y; acc1.z += v1.z; acc1.w += v1.w;
        }
        if (t < cnt) {
            int j0 = __shfl_sync(0xffffffffu, j, t);
            float4 v0 = *(const float4*)(hs + (size_t)j0 * F1 + lane * 4);
            acc0.x += v0.x; acc0.y += v0.y; acc0.z += v0.z; acc0.w += v0.w;
        }
    }
    float s = g_dinv[i];
    float4 bb = *(const float4*)(b1 + lane * 4);
    float f[4];
    f[0] = fmaxf(fmaf(acc0.x + acc1.x, s, bb.x), 0.f);
    f[1] = fmaxf(fmaf(acc0.y + acc1.y, s, bb.y), 0.f);
    f[2] = fmaxf(fmaf(acc0.z + acc1.z, s, bb.z), 0.f);
    f[3] = fmaxf(fmaf(acc0.w + acc1.w, s, bb.w), 0.f);

    float p[F2];
#pragma unroll
    for (int q = 0; q < F2; q++) {
        float4 w = *(const float4*)(&Wt[q][lane * 4]);
        p[q] = f[0] * w.x + f[1] * w.y + f[2] * w.z + f[3] * w.w;
    }
#pragma unroll
    for (int d = 16; d >= 1; d >>= 1) {
#pragma unroll
        for (int q = 0; q < F2; q++)
            p[q] += __shfl_xor_sync(0xffffffffu, p[q], d);
    }
    if (lane < 4) {
        float4 v = make_float4(p[lane * 4] * s, p[lane * 4 + 1] * s,
                               p[lane * 4 + 2] * s, p[lane * 4 + 3] * s);
        *(float4*)(g_h2 + (size_t)i * F2 + lane * 4) = v;
    }
}

// ---------------- Agg2: 4 threads per node, 16 dims, + b2 -------------------
__global__ void k_agg2(const float* __restrict__ b2, float* __restrict__ out, int n) {
    int gt = blockIdx.x * blockDim.x + threadIdx.x;
    int i = gt >> 2;
    if (i >= n) return;
    int q = (gt & 3) * 4;
    int beg = g_rowptr[i], end = g_rowptr[i + 1];
    const float* hs = g_h2;
    float4 acc = *(const float4*)(hs + (size_t)i * F2 + q);  // self loop
    for (int e = beg; e < end; e++) {
        int j = g_csr[e];
        float4 v = *(const float4*)(hs + (size_t)j * F2 + q);
        acc.x += v.x; acc.y += v.y; acc.z += v.z; acc.w += v.w;
    }
    float s = g_dinv[i];
    float4 bb = *(const float4*)(b2 + q);
    float4 r = make_float4(fmaf(acc.x, s, bb.x), fmaf(acc.y, s, bb.y),
                           fmaf(acc.z, s, bb.z), fmaf(acc.w, s, bb.w));
    *(float4*)(out + (size_t)i * F2 + q) = r;
}

// ---------------- launch: kernel launches ONLY -------------------------------
extern "C" void kernel_launch(void* const* d_in, const int* in_sizes, int n_in,
                              void* d_out, int out_size) {
    const float* x  = (const float*)d_in[0];
    const int*   ei = (const int*)d_in[1];    // int32 (JAX demotes int64)
    const float* W1 = (const float*)d_in[2];
    const float* b1 = (const float*)d_in[3];
    const float* W2 = (const float*)d_in[4];
    const float* b2 = (const float*)d_in[5];
    float* out = (float*)d_out;

    int n = in_sizes[0] / F0;       // 100000
    int E = in_sizes[1] / 2;        // 1600000

    int tb = 256;
    k_zero<<<(n + tb - 1) / tb, tb>>>(n);
    k_deg<<<(E + tb - 1) / tb, tb>>>(ei, E, n);
    k_dinv<<<(n + tb - 1) / tb, tb>>>(n);

    // gemm1 moved early: only needs x/W1/dinv; also lands in ncu's -s 5 window
    k_gemm1<<<(n + 127) / 128, 256>>>(x, W1, n);

    int nb = (n + 4095) / 4096;
    k_scan1<<<nb, 256>>>(n);
    k_scan2<<<1, 32>>>(nb);
    k_scan3<<<(n + tb - 1) / tb, tb>>>(n, E);
    k_fill<<<(E + tb - 1) / tb, tb>>>(ei, E, n);

    k_agg1<<<(n * 32 + tb - 1) / tb, tb>>>(b1, W2, n);
    k_agg2<<<(n * 4 + tb - 1) / tb, tb>>>(b2, out, n);
}

// round 7
// speedup vs baseline: 2.0272x; 2.0272x over previous
#include <cuda_runtime.h>
#include <cuda_bf16.h>
#include <math.h>

#define N_MAX 100000
#define E_MAX 1600000
#define F0 256
#define F1 128
#define F2 16

// ---------------- scratch (static device globals; no allocation) ------------
__device__ int   g_deg[N_MAX];
__device__ float g_dinv[N_MAX];
__device__ int   g_rowptr[N_MAX + 1];
__device__ int   g_cursor[N_MAX];
__device__ int   g_csr[E_MAX];
__device__ float g_h1[(size_t)N_MAX * F1];
__device__ float g_h2[(size_t)N_MAX * F2];
__device__ int   g_bsums[64];

// ---------------- packed f32x2 helpers (sm_103a) -----------------------------
__device__ __forceinline__ void ffma2(unsigned long long& d,
                                      unsigned long long a,
                                      unsigned long long b) {
    asm("fma.rn.f32x2 %0, %1, %2, %0;" : "+l"(d) : "l"(a), "l"(b));
}
__device__ __forceinline__ void unpack2(float& lo, float& hi, unsigned long long v) {
    asm("mov.b64 {%0, %1}, %2;" : "=f"(lo), "=f"(hi) : "l"(v));
}
__device__ __forceinline__ unsigned long long dup2(float a) {
    unsigned long long d;
    asm("mov.b64 %0, {%1, %1};" : "=l"(d) : "f"(a));
    return d;
}
__device__ __forceinline__ unsigned smem_u32(const void* p) {
    unsigned r;
    asm("{ .reg .u64 t; cvta.to.shared.u64 t, %1; cvt.u32.u64 %0, t; }"
        : "=r"(r) : "l"(p));
    return r;
}
__device__ __forceinline__ void cp_async16(unsigned dst, const void* src) {
    asm volatile("cp.async.ca.shared.global [%0], [%1], 16;"
                 :: "r"(dst), "l"(src));
}
__device__ __forceinline__ void cp_commit() {
    asm volatile("cp.async.commit_group;");
}
__device__ __forceinline__ void cp_wait0() {
    asm volatile("cp.async.wait_group 0;");
}

// ---------------- zero init --------------------------------------------------
__global__ void k_zero(int n) {
    int i = blockIdx.x * blockDim.x + threadIdx.x;
    if (i < n) g_deg[i] = 0;
}

// ---------------- degree histogram (edge_index is int32) ---------------------
__global__ void k_deg(const int* __restrict__ ei, int E, int n) {
    int i = blockIdx.x * blockDim.x + threadIdx.x;
    if (i < E) {
        int dst = ei[E + i];
        if ((unsigned)dst < (unsigned)n) atomicAdd(&g_deg[dst], 1);
    }
}

__global__ void k_dinv(int n) {
    int i = blockIdx.x * blockDim.x + threadIdx.x;
    if (i < n) g_dinv[i] = rsqrtf((float)(g_deg[i] + 1));
}

// ---------------- 3-phase exclusive scan (4096 elems / block) ---------------
__global__ void k_scan1(int n) {
    __shared__ int warpsum[8];
    int base = blockIdx.x * 4096;
    int t0 = base + threadIdx.x * 16;
    int vals[16];
    int s = 0;
#pragma unroll
    for (int j = 0; j < 16; j++) {
        int idx = t0 + j;
        int v = (idx < n) ? g_deg[idx] : 0;
        vals[j] = s;
        s += v;
    }
    int lane = threadIdx.x & 31, w = threadIdx.x >> 5;
    int x = s;
#pragma unroll
    for (int d = 1; d < 32; d <<= 1) {
        int y = __shfl_up_sync(0xffffffffu, x, d);
        if (lane >= d) x += y;
    }
    if (lane == 31) warpsum[w] = x;
    __syncthreads();
    if (w == 0 && lane < 8) {
        int y = warpsum[lane];
#pragma unroll
        for (int d = 1; d < 8; d <<= 1) {
            int z = __shfl_up_sync(0xffu, y, d);
            if (lane >= d) y += z;
        }
        warpsum[lane] = y;
    }
    __syncthreads();
    int warpoff = (w > 0) ? warpsum[w - 1] : 0;
    int throff = warpoff + x - s;
#pragma unroll
    for (int j = 0; j < 16; j++) {
        int idx = t0 + j;
        if (idx < n) g_rowptr[idx] = throff + vals[j];
    }
    if (threadIdx.x == 255) g_bsums[blockIdx.x] = warpoff + x;
}

__global__ void k_scan2(int nb) {
    if (threadIdx.x == 0 && blockIdx.x == 0) {
        int s = 0;
        for (int i = 0; i < nb; i++) { int v = g_bsums[i]; g_bsums[i] = s; s += v; }
    }
}

__global__ void k_scan3(int n, int E) {
    int i = blockIdx.x * blockDim.x + threadIdx.x;
    if (i < n) {
        int r = g_rowptr[i] + g_bsums[i >> 12];
        g_rowptr[i] = r;
        g_cursor[i] = r;
    }
    if (i == 0) g_rowptr[n] = E;
}

// ---------------- CSR fill ---------------------------------------------------
__global__ void k_fill(const int* __restrict__ ei, int E, int n) {
    int i = blockIdx.x * blockDim.x + threadIdx.x;
    if (i < E) {
        int dst = ei[E + i];
        int src = ei[i];
        if ((unsigned)dst < (unsigned)n && (unsigned)src < (unsigned)n) {
            int pos = atomicAdd(&g_cursor[dst], 1);
            g_csr[pos] = src;
        }
    }
}

// ---------------- GEMM1 v3: FFMA2 paired along N -----------------------------
// 128x128x16 double-buffered. B tile NORMAL (b-pairs free from LDS.128);
// a-operand duplicated via mov.b64 {a,a} on the alu pipe. B loaded by cp.async.
// Per thread per k: 4 LDS.128 + 8 dup + 32 FFMA2  -> LDS and fma both ~128cyc.
__global__ void __launch_bounds__(256) k_gemm1(
    const float* __restrict__ X, const float* __restrict__ W, int M) {
    __shared__ float As[2][16][128];
    __shared__ float Bs[2][16][128];
    int tid = threadIdx.x;
    int tx = tid & 15;           // col tile *8
    int ty = tid >> 4;           // row tile *8
    int m0 = blockIdx.x * 128;

    int arow = tid >> 2;         // 0..63 (and +64)
    int ac4  = (tid & 3) * 4;    // 0,4,8,12
    // B cp.async mapping: 512 float4 slots per tile, 2 per thread
    int bk0 = tid >> 5;          // slot tid:      k = tid>>5 (0..7)
    int bc0 = (tid & 31) * 4;
    int bk1 = 8 + (tid >> 5);    // slot tid+256:  k = 8..15
    unsigned bs_dst0[2], bs_dst1[2];
    bs_dst0[0] = smem_u32(&Bs[0][bk0][bc0]);
    bs_dst0[1] = smem_u32(&Bs[1][bk0][bc0]);
    bs_dst1[0] = smem_u32(&Bs[0][bk1][bc0]);
    bs_dst1[1] = smem_u32(&Bs[1][bk1][bc0]);

    unsigned long long acc2[8][4];
#pragma unroll
    for (int i = 0; i < 8; i++)
#pragma unroll
        for (int j = 0; j < 4; j++) acc2[i][j] = 0ULL;

    const float4 z4 = make_float4(0.f, 0.f, 0.f, 0.f);
    union U { float4 f; unsigned long long u[2]; };

    // preload tile 0
    {
        int gm0 = m0 + arow, gm1 = m0 + arow + 64;
        float4 va0 = (gm0 < M) ? *(const float4*)(X + (size_t)gm0 * F0 + ac4) : z4;
        float4 va1 = (gm1 < M) ? *(const float4*)(X + (size_t)gm1 * F0 + ac4) : z4;
        As[0][ac4 + 0][arow]      = va0.x;
        As[0][ac4 + 1][arow]      = va0.y;
        As[0][ac4 + 2][arow]      = va0.z;
        As[0][ac4 + 3][arow]      = va0.w;
        As[0][ac4 + 0][arow + 64] = va1.x;
        As[0][ac4 + 1][arow + 64] = va1.y;
        As[0][ac4 + 2][arow + 64] = va1.z;
        As[0][ac4 + 3][arow + 64] = va1.w;
        cp_async16(bs_dst0[0], W + (size_t)bk0 * F1 + bc0);
        cp_async16(bs_dst1[0], W + (size_t)bk1 * F1 + bc0);
        cp_commit();
    }
    cp_wait0();
    __syncthreads();

#pragma unroll 1
    for (int it = 0; it < 16; it++) {
        int cur = it & 1, nxt = cur ^ 1;
        float4 pa0, pa1;
        if (it < 15) {
            int k0 = (it + 1) * 16;
            int gm0 = m0 + arow, gm1 = m0 + arow + 64;
            pa0 = (gm0 < M) ? *(const float4*)(X + (size_t)gm0 * F0 + k0 + ac4) : z4;
            pa1 = (gm1 < M) ? *(const float4*)(X + (size_t)gm1 * F0 + k0 + ac4) : z4;
            cp_async16(bs_dst0[nxt], W + (size_t)(k0 + bk0) * F1 + bc0);
            cp_async16(bs_dst1[nxt], W + (size_t)(k0 + bk1) * F1 + bc0);
            cp_commit();
        }
#pragma unroll
        for (int k = 0; k < 16; k++) {
            U a0, a1, b0, b1;
            a0.f = *(const float4*)(&As[cur][k][ty * 8]);
            a1.f = *(const float4*)(&As[cur][k][ty * 8 + 4]);
            b0.f = *(const float4*)(&Bs[cur][k][tx * 8]);
            b1.f = *(const float4*)(&Bs[cur][k][tx * 8 + 4]);
            unsigned long long bp[4] = {b0.u[0], b0.u[1], b1.u[0], b1.u[1]};
            unsigned long long ad[8];
            ad[0] = dup2(a0.f.x); ad[1] = dup2(a0.f.y);
            ad[2] = dup2(a0.f.z); ad[3] = dup2(a0.f.w);
            ad[4] = dup2(a1.f.x); ad[5] = dup2(a1.f.y);
            ad[6] = dup2(a1.f.z); ad[7] = dup2(a1.f.w);
#pragma unroll
            for (int i = 0; i < 8; i++)
#pragma unroll
                for (int j = 0; j < 4; j++) ffma2(acc2[i][j], ad[i], bp[j]);
        }
        if (it < 15) {
            As[nxt][ac4 + 0][arow]      = pa0.x;
            As[nxt][ac4 + 1][arow]      = pa0.y;
            As[nxt][ac4 + 2][arow]      = pa0.z;
            As[nxt][ac4 + 3][arow]      = pa0.w;
            As[nxt][ac4 + 0][arow + 64] = pa1.x;
            As[nxt][ac4 + 1][arow + 64] = pa1.y;
            As[nxt][ac4 + 2][arow + 64] = pa1.z;
            As[nxt][ac4 + 3][arow + 64] = pa1.w;
            cp_wait0();
        }
        __syncthreads();
    }

    // epilogue: acc2[i][jp] = {C[row][tx*8+2jp], C[row][tx*8+2jp+1]}
#pragma unroll
    for (int i = 0; i < 8; i++) {
        int gm = m0 + ty * 8 + i;
        if (gm >= M) continue;
        float s = g_dinv[gm];
        float c0, c1, c2, c3, c4, c5, c6, c7;
        unpack2(c0, c1, acc2[i][0]);
        unpack2(c2, c3, acc2[i][1]);
        unpack2(c4, c5, acc2[i][2]);
        unpack2(c6, c7, acc2[i][3]);
        *(float4*)(g_h1 + (size_t)gm * F1 + tx * 8) =
            make_float4(c0 * s, c1 * s, c2 * s, c3 * s);
        *(float4*)(g_h1 + (size_t)gm * F1 + tx * 8 + 4) =
            make_float4(c4 * s, c5 * s, c6 * s, c7 * s);
    }
}

// ---------------- Agg1 + fused GEMM2 ----------------------------------------
__global__ void __launch_bounds__(256) k_agg1(
    const float* __restrict__ b1, const float* __restrict__ W2, int n) {
    __shared__ float Wt[F2][F1];
    for (int idx = threadIdx.x; idx < (F1 * F2) / 4; idx += 256) {
        int k = idx >> 2;
        int q4 = (idx & 3) * 4;
        float4 v = *(const float4*)(W2 + (size_t)k * F2 + q4);
        Wt[q4 + 0][k] = v.x;
        Wt[q4 + 1][k] = v.y;
        Wt[q4 + 2][k] = v.z;
        Wt[q4 + 3][k] = v.w;
    }
    __syncthreads();

    int warp = (blockIdx.x * blockDim.x + threadIdx.x) >> 5;
    int lane = threadIdx.x & 31;
    if (warp >= n) return;
    int i = warp;
    int beg = g_rowptr[i], end = g_rowptr[i + 1];
    const float* hs = g_h1;
    float4 acc0 = *(const float4*)(hs + (size_t)i * F1 + lane * 4);
    float4 acc1 = make_float4(0.f, 0.f, 0.f, 0.f);
    for (int e = beg; e < end; e += 32) {
        int cnt = min(32, end - e);
        int j = (e + lane < end) ? g_csr[e + lane] : 0;
        int t = 0;
        for (; t + 1 < cnt; t += 2) {
            int j0 = __shfl_sync(0xffffffffu, j, t);
            int j1 = __shfl_sync(0xffffffffu, j, t + 1);
            float4 v0 = *(const float4*)(hs + (size_t)j0 * F1 + lane * 4);
            float4 v1 = *(const float4*)(hs + (size_t)j1 * F1 + lane * 4);
            acc0.x += v0.x; acc0.y += v0.y; acc0.z += v0.z; acc0.w += v0.w;
            acc1.x += v1.x; acc1.y += v1.y; acc1.z += v1.z; acc1.w += v1.w;
        }
        if (t < cnt) {
            int j0 = __shfl_sync(0xffffffffu, j, t);
            float4 v0 = *(const float4*)(hs + (size_t)j0 * F1 + lane * 4);
            acc0.x += v0.x; acc0.y += v0.y; acc0.z += v0.z; acc0.w += v0.w;
        }
    }
    float s = g_dinv[i];
    float4 bb = *(const float4*)(b1 + lane * 4);
    float f[4];
    f[0] = fmaxf(fmaf(acc0.x + acc1.x, s, bb.x), 0.f);
    f[1] = fmaxf(fmaf(acc0.y + acc1.y, s, bb.y), 0.f);
    f[2] = fmaxf(fmaf(acc0.z + acc1.z, s, bb.z), 0.f);
    f[3] = fmaxf(fmaf(acc0.w + acc1.w, s, bb.w), 0.f);

    float p[F2];
#pragma unroll
    for (int q = 0; q < F2; q++) {
        float4 w = *(const float4*)(&Wt[q][lane * 4]);
        p[q] = f[0] * w.x + f[1] * w.y + f[2] * w.z + f[3] * w.w;
    }
#pragma unroll
    for (int d = 16; d >= 1; d >>= 1) {
#pragma unroll
        for (int q = 0; q < F2; q++)
            p[q] += __shfl_xor_sync(0xffffffffu, p[q], d);
    }
    if (lane < 4) {
        float4 v = make_float4(p[lane * 4] * s, p[lane * 4 + 1] * s,
                               p[lane * 4 + 2] * s, p[lane * 4 + 3] * s);
        *(float4*)(g_h2 + (size_t)i * F2 + lane * 4) = v;
    }
}

// ---------------- Agg2: 4 threads per node, 16 dims, + b2 -------------------
__global__ void k_agg2(const float* __restrict__ b2, float* __restrict__ out, int n) {
    int gt = blockIdx.x * blockDim.x + threadIdx.x;
    int i = gt >> 2;
    if (i >= n) return;
    int q = (gt & 3) * 4;
    int beg = g_rowptr[i], end = g_rowptr[i + 1];
    const float* hs = g_h2;
    float4 acc = *(const float4*)(hs + (size_t)i * F2 + q);
    for (int e = beg; e < end; e++) {
        int j = g_csr[e];
        float4 v = *(const float4*)(hs + (size_t)j * F2 + q);
        acc.x += v.x; acc.y += v.y; acc.z += v.z; acc.w += v.w;
    }
    float s = g_dinv[i];
    float4 bb = *(const float4*)(b2 + q);
    float4 r = make_float4(fmaf(acc.x, s, bb.x), fmaf(acc.y, s, bb.y),
                           fmaf(acc.z, s, bb.z), fmaf(acc.w, s, bb.w));
    *(float4*)(out + (size_t)i * F2 + q) = r;
}

// ---------------- launch: kernel launches ONLY -------------------------------
extern "C" void kernel_launch(void* const* d_in, const int* in_sizes, int n_in,
                              void* d_out, int out_size) {
    const float* x  = (const float*)d_in[0];
    const int*   ei = (const int*)d_in[1];
    const float* W1 = (const float*)d_in[2];
    const float* b1 = (const float*)d_in[3];
    const float* W2 = (const float*)d_in[4];
    const float* b2 = (const float*)d_in[5];
    float* out = (float*)d_out;

    int n = in_sizes[0] / F0;       // 100000
    int E = in_sizes[1] / 2;        // 1600000

    int tb = 256;
    k_zero<<<(n + tb - 1) / tb, tb>>>(n);
    k_deg<<<(E + tb - 1) / tb, tb>>>(ei, E, n);
    k_dinv<<<(n + tb - 1) / tb, tb>>>(n);

    // gemm1 4th so it lands in ncu's -s 5 window
    k_gemm1<<<(n + 127) / 128, 256>>>(x, W1, n);

    int nb = (n + 4095) / 4096;
    k_scan1<<<nb, 256>>>(n);
    k_scan2<<<1, 32>>>(nb);
    k_scan3<<<(n + tb - 1) / tb, tb>>>(n, E);
    k_fill<<<(E + tb - 1) / tb, tb>>>(ei, E, n);

    k_agg1<<<(n * 32 + tb - 1) / tb, tb>>>(b1, W2, n);
    k_agg2<<<(n * 4 + tb - 1) / tb, tb>>>(b2, out, n);
}

// round 9
// speedup vs baseline: 2.2518x; 1.1108x over previous
#include <cuda_runtime.h>
#include <cuda_bf16.h>
#include <math.h>

#define N_MAX 100000
#define E_MAX 1600000
#define F0 256
#define F1 128
#define F2 16

// ---------------- scratch (static device globals; no allocation) ------------
__device__ int   g_deg[N_MAX];
__device__ float g_dinv[N_MAX];
__device__ int   g_rowptr[N_MAX + 1];
__device__ int   g_cursor[N_MAX];
__device__ int   g_csr[E_MAX];
__device__ float g_h1[(size_t)N_MAX * F1];
__device__ float g_h2[(size_t)N_MAX * F2];
__device__ int   g_bsums[64];

// ---------------- packed f32x2 helpers (sm_103a) -----------------------------
__device__ __forceinline__ void ffma2(unsigned long long& d,
                                      unsigned long long a,
                                      unsigned long long b) {
    asm("fma.rn.f32x2 %0, %1, %2, %0;" : "+l"(d) : "l"(a), "l"(b));
}
__device__ __forceinline__ void unpack2(float& lo, float& hi, unsigned long long v) {
    asm("mov.b64 {%0, %1}, %2;" : "=f"(lo), "=f"(hi) : "l"(v));
}
__device__ __forceinline__ unsigned long long dup2(float a) {
    unsigned long long d;
    asm("mov.b64 %0, {%1, %1};" : "=l"(d) : "f"(a));
    return d;
}
__device__ __forceinline__ unsigned smem_u32(const void* p) {
    unsigned r;
    asm("{ .reg .u64 t; cvta.to.shared.u64 t, %1; cvt.u32.u64 %0, t; }"
        : "=r"(r) : "l"(p));
    return r;
}
__device__ __forceinline__ void cp_async16(unsigned dst, const void* src) {
    asm volatile("cp.async.ca.shared.global [%0], [%1], 16;"
                 :: "r"(dst), "l"(src));
}
__device__ __forceinline__ void cp_commit() {
    asm volatile("cp.async.commit_group;");
}
__device__ __forceinline__ void cp_wait0() {
    asm volatile("cp.async.wait_group 0;");
}

// ---------------- zero init --------------------------------------------------
__global__ void k_zero(int n) {
    int i = blockIdx.x * blockDim.x + threadIdx.x;
    if (i < n) g_deg[i] = 0;
}

// ---------------- degree histogram (edge_index is int32) ---------------------
__global__ void k_deg(const int* __restrict__ ei, int E, int n) {
    int i = blockIdx.x * blockDim.x + threadIdx.x;
    if (i < E) {
        int dst = ei[E + i];
        if ((unsigned)dst < (unsigned)n) atomicAdd(&g_deg[dst], 1);
    }
}

__global__ void k_dinv(int n) {
    int i = blockIdx.x * blockDim.x + threadIdx.x;
    if (i < n) g_dinv[i] = rsqrtf((float)(g_deg[i] + 1));
}

// ---------------- 3-phase exclusive scan (4096 elems / block) ---------------
__global__ void k_scan1(int n) {
    __shared__ int warpsum[8];
    int base = blockIdx.x * 4096;
    int t0 = base + threadIdx.x * 16;
    int vals[16];
    int s = 0;
#pragma unroll
    for (int j = 0; j < 16; j++) {
        int idx = t0 + j;
        int v = (idx < n) ? g_deg[idx] : 0;
        vals[j] = s;
        s += v;
    }
    int lane = threadIdx.x & 31, w = threadIdx.x >> 5;
    int x = s;
#pragma unroll
    for (int d = 1; d < 32; d <<= 1) {
        int y = __shfl_up_sync(0xffffffffu, x, d);
        if (lane >= d) x += y;
    }
    if (lane == 31) warpsum[w] = x;
    __syncthreads();
    if (w == 0 && lane < 8) {
        int y = warpsum[lane];
#pragma unroll
        for (int d = 1; d < 8; d <<= 1) {
            int z = __shfl_up_sync(0xffu, y, d);
            if (lane >= d) y += z;
        }
        warpsum[lane] = y;
    }
    __syncthreads();
    int warpoff = (w > 0) ? warpsum[w - 1] : 0;
    int throff = warpoff + x - s;
#pragma unroll
    for (int j = 0; j < 16; j++) {
        int idx = t0 + j;
        if (idx < n) g_rowptr[idx] = throff + vals[j];
    }
    if (threadIdx.x == 255) g_bsums[blockIdx.x] = warpoff + x;
}

__global__ void k_scan2(int nb) {
    if (threadIdx.x == 0 && blockIdx.x == 0) {
        int s = 0;
        for (int i = 0; i < nb; i++) { int v = g_bsums[i]; g_bsums[i] = s; s += v; }
    }
}

__global__ void k_scan3(int n, int E) {
    int i = blockIdx.x * blockDim.x + threadIdx.x;
    if (i < n) {
        int r = g_rowptr[i] + g_bsums[i >> 12];
        g_rowptr[i] = r;
        g_cursor[i] = r;
    }
    if (i == 0) g_rowptr[n] = E;
}

// ---------------- CSR fill ---------------------------------------------------
__global__ void k_fill(const int* __restrict__ ei, int E, int n) {
    int i = blockIdx.x * blockDim.x + threadIdx.x;
    if (i < E) {
        int dst = ei[E + i];
        int src = ei[i];
        if ((unsigned)dst < (unsigned)n && (unsigned)src < (unsigned)n) {
            int pos = atomicAdd(&g_cursor[dst], 1);
            g_csr[pos] = src;
        }
    }
}

// ---------------- GEMM1: FFMA2 paired along N (R7, 162us) --------------------
__global__ void __launch_bounds__(256) k_gemm1(
    const float* __restrict__ X, const float* __restrict__ W, int M) {
    __shared__ float As[2][16][128];
    __shared__ float Bs[2][16][128];
    int tid = threadIdx.x;
    int tx = tid & 15;
    int ty = tid >> 4;
    int m0 = blockIdx.x * 128;

    int arow = tid >> 2;
    int ac4  = (tid & 3) * 4;
    int bk0 = tid >> 5;
    int bc0 = (tid & 31) * 4;
    int bk1 = 8 + (tid >> 5);
    unsigned bs_dst0[2], bs_dst1[2];
    bs_dst0[0] = smem_u32(&Bs[0][bk0][bc0]);
    bs_dst0[1] = smem_u32(&Bs[1][bk0][bc0]);
    bs_dst1[0] = smem_u32(&Bs[0][bk1][bc0]);
    bs_dst1[1] = smem_u32(&Bs[1][bk1][bc0]);

    unsigned long long acc2[8][4];
#pragma unroll
    for (int i = 0; i < 8; i++)
#pragma unroll
        for (int j = 0; j < 4; j++) acc2[i][j] = 0ULL;

    const float4 z4 = make_float4(0.f, 0.f, 0.f, 0.f);
    union U { float4 f; unsigned long long u[2]; };

    {
        int gm0 = m0 + arow, gm1 = m0 + arow + 64;
        float4 va0 = (gm0 < M) ? *(const float4*)(X + (size_t)gm0 * F0 + ac4) : z4;
        float4 va1 = (gm1 < M) ? *(const float4*)(X + (size_t)gm1 * F0 + ac4) : z4;
        As[0][ac4 + 0][arow]      = va0.x;
        As[0][ac4 + 1][arow]      = va0.y;
        As[0][ac4 + 2][arow]      = va0.z;
        As[0][ac4 + 3][arow]      = va0.w;
        As[0][ac4 + 0][arow + 64] = va1.x;
        As[0][ac4 + 1][arow + 64] = va1.y;
        As[0][ac4 + 2][arow + 64] = va1.z;
        As[0][ac4 + 3][arow + 64] = va1.w;
        cp_async16(bs_dst0[0], W + (size_t)bk0 * F1 + bc0);
        cp_async16(bs_dst1[0], W + (size_t)bk1 * F1 + bc0);
        cp_commit();
    }
    cp_wait0();
    __syncthreads();

#pragma unroll 1
    for (int it = 0; it < 16; it++) {
        int cur = it & 1, nxt = cur ^ 1;
        float4 pa0, pa1;
        if (it < 15) {
            int k0 = (it + 1) * 16;
            int gm0 = m0 + arow, gm1 = m0 + arow + 64;
            pa0 = (gm0 < M) ? *(const float4*)(X + (size_t)gm0 * F0 + k0 + ac4) : z4;
            pa1 = (gm1 < M) ? *(const float4*)(X + (size_t)gm1 * F0 + k0 + ac4) : z4;
            cp_async16(bs_dst0[nxt], W + (size_t)(k0 + bk0) * F1 + bc0);
            cp_async16(bs_dst1[nxt], W + (size_t)(k0 + bk1) * F1 + bc0);
            cp_commit();
        }
#pragma unroll
        for (int k = 0; k < 16; k++) {
            U a0, a1, b0, b1;
            a0.f = *(const float4*)(&As[cur][k][ty * 8]);
            a1.f = *(const float4*)(&As[cur][k][ty * 8 + 4]);
            b0.f = *(const float4*)(&Bs[cur][k][tx * 8]);
            b1.f = *(const float4*)(&Bs[cur][k][tx * 8 + 4]);
            unsigned long long bp[4] = {b0.u[0], b0.u[1], b1.u[0], b1.u[1]};
            unsigned long long ad[8];
            ad[0] = dup2(a0.f.x); ad[1] = dup2(a0.f.y);
            ad[2] = dup2(a0.f.z); ad[3] = dup2(a0.f.w);
            ad[4] = dup2(a1.f.x); ad[5] = dup2(a1.f.y);
            ad[6] = dup2(a1.f.z); ad[7] = dup2(a1.f.w);
#pragma unroll
            for (int i = 0; i < 8; i++)
#pragma unroll
                for (int j = 0; j < 4; j++) ffma2(acc2[i][j], ad[i], bp[j]);
        }
        if (it < 15) {
            As[nxt][ac4 + 0][arow]      = pa0.x;
            As[nxt][ac4 + 1][arow]      = pa0.y;
            As[nxt][ac4 + 2][arow]      = pa0.z;
            As[nxt][ac4 + 3][arow]      = pa0.w;
            As[nxt][ac4 + 0][arow + 64] = pa1.x;
            As[nxt][ac4 + 1][arow + 64] = pa1.y;
            As[nxt][ac4 + 2][arow + 64] = pa1.z;
            As[nxt][ac4 + 3][arow + 64] = pa1.w;
            cp_wait0();
        }
        __syncthreads();
    }

#pragma unroll
    for (int i = 0; i < 8; i++) {
        int gm = m0 + ty * 8 + i;
        if (gm >= M) continue;
        float s = g_dinv[gm];
        float c0, c1, c2, c3, c4, c5, c6, c7;
        unpack2(c0, c1, acc2[i][0]);
        unpack2(c2, c3, acc2[i][1]);
        unpack2(c4, c5, acc2[i][2]);
        unpack2(c6, c7, acc2[i][3]);
        *(float4*)(g_h1 + (size_t)gm * F1 + tx * 8) =
            make_float4(c0 * s, c1 * s, c2 * s, c3 * s);
        *(float4*)(g_h1 + (size_t)gm * F1 + tx * 8 + 4) =
            make_float4(c4 * s, c5 * s, c6 * s, c7 * s);
    }
}

// ---------------- Agg1 + fused GEMM2 ----------------------------------------
__global__ void __launch_bounds__(256) k_agg1(
    const float* __restrict__ b1, const float* __restrict__ W2, int n) {
    __shared__ float Wt[F2][F1];
    for (int idx = threadIdx.x; idx < (F1 * F2) / 4; idx += 256) {
        int k = idx >> 2;
        int q4 = (idx & 3) * 4;
        float4 v = *(const float4*)(W2 + (size_t)k * F2 + q4);
        Wt[q4 + 0][k] = v.x;
        Wt[q4 + 1][k] = v.y;
        Wt[q4 + 2][k] = v.z;
        Wt[q4 + 3][k] = v.w;
    }
    __syncthreads();

    int warp = (blockIdx.x * blockDim.x + threadIdx.x) >> 5;
    int lane = threadIdx.x & 31;
    if (warp >= n) return;
    int i = warp;
    int beg = g_rowptr[i], end = g_rowptr[i + 1];
    const float* hs = g_h1;
    float4 acc0 = *(const float4*)(hs + (size_t)i * F1 + lane * 4);
    float4 acc1 = make_float4(0.f, 0.f, 0.f, 0.f);
    for (int e = beg; e < end; e += 32) {
        int cnt = min(32, end - e);
        int j = (e + lane < end) ? g_csr[e + lane] : 0;
        int t = 0;
        for (; t + 1 < cnt; t += 2) {
            int j0 = __shfl_sync(0xffffffffu, j, t);
            int j1 = __shfl_sync(0xffffffffu, j, t + 1);
            float4 v0 = *(const float4*)(hs + (size_t)j0 * F1 + lane * 4);
            float4 v1 = *(const float4*)(hs + (size_t)j1 * F1 + lane * 4);
            acc0.x += v0.x; acc0.y += v0.y; acc0.z += v0.z; acc0.w += v0.w;
            acc1.x += v1.x; acc1.y += v1.y; acc1.z += v1.z; acc1.w += v1.w;
        }
        if (t < cnt) {
            int j0 = __shfl_sync(0xffffffffu, j, t);
            float4 v0 = *(const float4*)(hs + (size_t)j0 * F1 + lane * 4);
            acc0.x += v0.x; acc0.y += v0.y; acc0.z += v0.z; acc0.w += v0.w;
        }
    }
    float s = g_dinv[i];
    float4 bb = *(const float4*)(b1 + lane * 4);
    float f[4];
    f[0] = fmaxf(fmaf(acc0.x + acc1.x, s, bb.x), 0.f);
    f[1] = fmaxf(fmaf(acc0.y + acc1.y, s, bb.y), 0.f);
    f[2] = fmaxf(fmaf(acc0.z + acc1.z, s, bb.z), 0.f);
    f[3] = fmaxf(fmaf(acc0.w + acc1.w, s, bb.w), 0.f);

    float p[F2];
#pragma unroll
    for (int q = 0; q < F2; q++) {
        float4 w = *(const float4*)(&Wt[q][lane * 4]);
        p[q] = f[0] * w.x + f[1] * w.y + f[2] * w.z + f[3] * w.w;
    }
#pragma unroll
    for (int d = 16; d >= 1; d >>= 1) {
#pragma unroll
        for (int q = 0; q < F2; q++)
            p[q] += __shfl_xor_sync(0xffffffffu, p[q], d);
    }
    if (lane < 4) {
        float4 v = make_float4(p[lane * 4] * s, p[lane * 4 + 1] * s,
                               p[lane * 4 + 2] * s, p[lane * 4 + 3] * s);
        *(float4*)(g_h2 + (size_t)i * F2 + lane * 4) = v;
    }
}

// ---------------- Agg2: 4 threads per node, 16 dims, + b2 -------------------
__global__ void k_agg2(const float* __restrict__ b2, float* __restrict__ out, int n) {
    int gt = blockIdx.x * blockDim.x + threadIdx.x;
    int i = gt >> 2;
    if (i >= n) return;
    int q = (gt & 3) * 4;
    int beg = g_rowptr[i], end = g_rowptr[i + 1];
    const float* hs = g_h2;
    float4 acc = *(const float4*)(hs + (size_t)i * F2 + q);
    for (int e = beg; e < end; e++) {
        int j = g_csr[e];
        float4 v = *(const float4*)(hs + (size_t)j * F2 + q);
        acc.x += v.x; acc.y += v.y; acc.z += v.z; acc.w += v.w;
    }
    float s = g_dinv[i];
    float4 bb = *(const float4*)(b2 + q);
    float4 r = make_float4(fmaf(acc.x, s, bb.x), fmaf(acc.y, s, bb.y),
                           fmaf(acc.z, s, bb.z), fmaf(acc.w, s, bb.w));
    *(float4*)(out + (size_t)i * F2 + q) = r;
}

// ---------------- launch: fork/join graph ------------------------------------
// Default stream: zero -> deg -> dinv -> gemm1 --------\
// Side stream:                 \-> scan1..3 -> fill ----+-> agg1 -> agg2
// Streams/events created lazily on the FIRST (correctness) call, so the
// capture call issues only launches + event record/wait (graph-legal).
extern "C" void kernel_launch(void* const* d_in, const int* in_sizes, int n_in,
                              void* d_out, int out_size) {
    const float* x  = (const float*)d_in[0];
    const int*   ei = (const int*)d_in[1];
    const float* W1 = (const float*)d_in[2];
    const float* b1 = (const float*)d_in[3];
    const float* W2 = (const float*)d_in[4];
    const float* b2 = (const float*)d_in[5];
    float* out = (float*)d_out;

    int n = in_sizes[0] / F0;       // 100000
    int E = in_sizes[1] / 2;        // 1600000

    static cudaStream_t s2 = 0;
    static cudaEvent_t evFork = 0, evJoin = 0;
    if (!s2) {
        cudaStreamCreateWithFlags(&s2, cudaStreamNonBlocking);
        cudaEventCreateWithFlags(&evFork, cudaEventDisableTiming);
        cudaEventCreateWithFlags(&evJoin, cudaEventDisableTiming);
    }

    int tb = 256;
    k_zero<<<(n + tb - 1) / tb, tb>>>(n);
    k_deg<<<(E + tb - 1) / tb, tb>>>(ei, E, n);

    // fork: CSR build (scan+fill) runs on s2, concurrent with dinv+gemm1
    cudaEventRecord(evFork, 0);
    cudaStreamWaitEvent(s2, evFork, 0);

    k_dinv<<<(n + tb - 1) / tb, tb>>>(n);
    k_gemm1<<<(n + 127) / 128, 256>>>(x, W1, n);

    int nb = (n + 4095) / 4096;
    k_scan1<<<nb, 256, 0, s2>>>(n);
    k_scan2<<<1, 32, 0, s2>>>(nb);
    k_scan3<<<(n + tb - 1) / tb, tb, 0, s2>>>(n, E);
    k_fill<<<(E + tb - 1) / tb, tb, 0, s2>>>(ei, E, n);
    cudaEventRecord(evJoin, s2);

    // join: agg1 needs gemm1 (default stream) AND csr (s2)
    cudaStreamWaitEvent(0, evJoin, 0);
    k_agg1<<<(n * 32 + tb - 1) / tb, tb>>>(b1, W2, n);
    k_agg2<<<(n * 4 + tb - 1) / tb, tb>>>(b2, out, n);
}

// round 10
// speedup vs baseline: 2.3828x; 1.0582x over previous
#include <cuda_runtime.h>
#include <cuda_bf16.h>
#include <cuda_fp16.h>
#include <math.h>

#define N_MAX 100000
#define E_MAX 1600000
#define F0 256
#define F1 128
#define F2 16

// ---------------- scratch (static device globals; no allocation) ------------
__device__ int      g_deg[N_MAX];
__device__ float    g_dinv[N_MAX];
__device__ int      g_rowptr[N_MAX + 1];
__device__ int      g_cursor[N_MAX];
__device__ int      g_csr[E_MAX];
__device__ unsigned g_h1h[(size_t)N_MAX * F1 / 2];  // h1 as half2 pairs
__device__ float    g_h2[(size_t)N_MAX * F2];
__device__ int      g_bsums[64];

// ---------------- packed f32x2 helpers (sm_103a) -----------------------------
__device__ __forceinline__ void ffma2(unsigned long long& d,
                                      unsigned long long a,
                                      unsigned long long b) {
    asm("fma.rn.f32x2 %0, %1, %2, %0;" : "+l"(d) : "l"(a), "l"(b));
}
__device__ __forceinline__ void unpack2(float& lo, float& hi, unsigned long long v) {
    asm("mov.b64 {%0, %1}, %2;" : "=f"(lo), "=f"(hi) : "l"(v));
}
__device__ __forceinline__ unsigned long long dup2(float a) {
    unsigned long long d;
    asm("mov.b64 %0, {%1, %1};" : "=l"(d) : "f"(a));
    return d;
}
__device__ __forceinline__ unsigned smem_u32(const void* p) {
    unsigned r;
    asm("{ .reg .u64 t; cvta.to.shared.u64 t, %1; cvt.u32.u64 %0, t; }"
        : "=r"(r) : "l"(p));
    return r;
}
__device__ __forceinline__ void cp_async16(unsigned dst, const void* src) {
    asm volatile("cp.async.ca.shared.global [%0], [%1], 16;"
                 :: "r"(dst), "l"(src));
}
__device__ __forceinline__ void cp_commit() {
    asm volatile("cp.async.commit_group;");
}
__device__ __forceinline__ void cp_wait0() {
    asm volatile("cp.async.wait_group 0;");
}
__device__ __forceinline__ unsigned pack_h2(float a, float b) {
    __half2 h = __floats2half2_rn(a, b);
    return *(unsigned*)&h;
}

// ---------------- zero init --------------------------------------------------
__global__ void k_zero(int n) {
    int i = blockIdx.x * blockDim.x + threadIdx.x;
    if (i < n) g_deg[i] = 0;
}

// ---------------- degree histogram (edge_index is int32) ---------------------
__global__ void k_deg(const int* __restrict__ ei, int E, int n) {
    int i = blockIdx.x * blockDim.x + threadIdx.x;
    if (i < E) {
        int dst = ei[E + i];
        if ((unsigned)dst < (unsigned)n) atomicAdd(&g_deg[dst], 1);
    }
}

__global__ void k_dinv(int n) {
    int i = blockIdx.x * blockDim.x + threadIdx.x;
    if (i < n) g_dinv[i] = rsqrtf((float)(g_deg[i] + 1));
}

// ---------------- 3-phase exclusive scan (4096 elems / block) ---------------
__global__ void k_scan1(int n) {
    __shared__ int warpsum[8];
    int base = blockIdx.x * 4096;
    int t0 = base + threadIdx.x * 16;
    int vals[16];
    int s = 0;
#pragma unroll
    for (int j = 0; j < 16; j++) {
        int idx = t0 + j;
        int v = (idx < n) ? g_deg[idx] : 0;
        vals[j] = s;
        s += v;
    }
    int lane = threadIdx.x & 31, w = threadIdx.x >> 5;
    int x = s;
#pragma unroll
    for (int d = 1; d < 32; d <<= 1) {
        int y = __shfl_up_sync(0xffffffffu, x, d);
        if (lane >= d) x += y;
    }
    if (lane == 31) warpsum[w] = x;
    __syncthreads();
    if (w == 0 && lane < 8) {
        int y = warpsum[lane];
#pragma unroll
        for (int d = 1; d < 8; d <<= 1) {
            int z = __shfl_up_sync(0xffu, y, d);
            if (lane >= d) y += z;
        }
        warpsum[lane] = y;
    }
    __syncthreads();
    int warpoff = (w > 0) ? warpsum[w - 1] : 0;
    int throff = warpoff + x - s;
#pragma unroll
    for (int j = 0; j < 16; j++) {
        int idx = t0 + j;
        if (idx < n) g_rowptr[idx] = throff + vals[j];
    }
    if (threadIdx.x == 255) g_bsums[blockIdx.x] = warpoff + x;
}

__global__ void k_scan2(int nb) {
    if (threadIdx.x == 0 && blockIdx.x == 0) {
        int s = 0;
        for (int i = 0; i < nb; i++) { int v = g_bsums[i]; g_bsums[i] = s; s += v; }
    }
}

__global__ void k_scan3(int n, int E) {
    int i = blockIdx.x * blockDim.x + threadIdx.x;
    if (i < n) {
        int r = g_rowptr[i] + g_bsums[i >> 12];
        g_rowptr[i] = r;
        g_cursor[i] = r;
    }
    if (i == 0) g_rowptr[n] = E;
}

// ---------------- CSR fill ---------------------------------------------------
__global__ void k_fill(const int* __restrict__ ei, int E, int n) {
    int i = blockIdx.x * blockDim.x + threadIdx.x;
    if (i < E) {
        int dst = ei[E + i];
        int src = ei[i];
        if ((unsigned)dst < (unsigned)n && (unsigned)src < (unsigned)n) {
            int pos = atomicAdd(&g_cursor[dst], 1);
            g_csr[pos] = src;
        }
    }
}

// ---------------- GEMM1: FFMA2 paired along N, fp16 output -------------------
__global__ void __launch_bounds__(256) k_gemm1(
    const float* __restrict__ X, const float* __restrict__ W, int M) {
    __shared__ float As[2][16][128];
    __shared__ float Bs[2][16][128];
    int tid = threadIdx.x;
    int tx = tid & 15;
    int ty = tid >> 4;
    int m0 = blockIdx.x * 128;

    int arow = tid >> 2;
    int ac4  = (tid & 3) * 4;
    int bk0 = tid >> 5;
    int bc0 = (tid & 31) * 4;
    int bk1 = 8 + (tid >> 5);
    unsigned bs_dst0[2], bs_dst1[2];
    bs_dst0[0] = smem_u32(&Bs[0][bk0][bc0]);
    bs_dst0[1] = smem_u32(&Bs[1][bk0][bc0]);
    bs_dst1[0] = smem_u32(&Bs[0][bk1][bc0]);
    bs_dst1[1] = smem_u32(&Bs[1][bk1][bc0]);

    unsigned long long acc2[8][4];
#pragma unroll
    for (int i = 0; i < 8; i++)
#pragma unroll
        for (int j = 0; j < 4; j++) acc2[i][j] = 0ULL;

    const float4 z4 = make_float4(0.f, 0.f, 0.f, 0.f);
    union U { float4 f; unsigned long long u[2]; };

    {
        int gm0 = m0 + arow, gm1 = m0 + arow + 64;
        float4 va0 = (gm0 < M) ? *(const float4*)(X + (size_t)gm0 * F0 + ac4) : z4;
        float4 va1 = (gm1 < M) ? *(const float4*)(X + (size_t)gm1 * F0 + ac4) : z4;
        As[0][ac4 + 0][arow]      = va0.x;
        As[0][ac4 + 1][arow]      = va0.y;
        As[0][ac4 + 2][arow]      = va0.z;
        As[0][ac4 + 3][arow]      = va0.w;
        As[0][ac4 + 0][arow + 64] = va1.x;
        As[0][ac4 + 1][arow + 64] = va1.y;
        As[0][ac4 + 2][arow + 64] = va1.z;
        As[0][ac4 + 3][arow + 64] = va1.w;
        cp_async16(bs_dst0[0], W + (size_t)bk0 * F1 + bc0);
        cp_async16(bs_dst1[0], W + (size_t)bk1 * F1 + bc0);
        cp_commit();
    }
    cp_wait0();
    __syncthreads();

#pragma unroll 1
    for (int it = 0; it < 16; it++) {
        int cur = it & 1, nxt = cur ^ 1;
        float4 pa0, pa1;
        if (it < 15) {
            int k0 = (it + 1) * 16;
            int gm0 = m0 + arow, gm1 = m0 + arow + 64;
            pa0 = (gm0 < M) ? *(const float4*)(X + (size_t)gm0 * F0 + k0 + ac4) : z4;
            pa1 = (gm1 < M) ? *(const float4*)(X + (size_t)gm1 * F0 + k0 + ac4) : z4;
            cp_async16(bs_dst0[nxt], W + (size_t)(k0 + bk0) * F1 + bc0);
            cp_async16(bs_dst1[nxt], W + (size_t)(k0 + bk1) * F1 + bc0);
            cp_commit();
        }
#pragma unroll
        for (int k = 0; k < 16; k++) {
            U a0, a1, b0, b1;
            a0.f = *(const float4*)(&As[cur][k][ty * 8]);
            a1.f = *(const float4*)(&As[cur][k][ty * 8 + 4]);
            b0.f = *(const float4*)(&Bs[cur][k][tx * 8]);
            b1.f = *(const float4*)(&Bs[cur][k][tx * 8 + 4]);
            unsigned long long bp[4] = {b0.u[0], b0.u[1], b1.u[0], b1.u[1]};
            unsigned long long ad[8];
            ad[0] = dup2(a0.f.x); ad[1] = dup2(a0.f.y);
            ad[2] = dup2(a0.f.z); ad[3] = dup2(a0.f.w);
            ad[4] = dup2(a1.f.x); ad[5] = dup2(a1.f.y);
            ad[6] = dup2(a1.f.z); ad[7] = dup2(a1.f.w);
#pragma unroll
            for (int i = 0; i < 8; i++)
#pragma unroll
                for (int j = 0; j < 4; j++) ffma2(acc2[i][j], ad[i], bp[j]);
        }
        if (it < 15) {
            As[nxt][ac4 + 0][arow]      = pa0.x;
            As[nxt][ac4 + 1][arow]      = pa0.y;
            As[nxt][ac4 + 2][arow]      = pa0.z;
            As[nxt][ac4 + 3][arow]      = pa0.w;
            As[nxt][ac4 + 0][arow + 64] = pa1.x;
            As[nxt][ac4 + 1][arow + 64] = pa1.y;
            As[nxt][ac4 + 2][arow + 64] = pa1.z;
            As[nxt][ac4 + 3][arow + 64] = pa1.w;
            cp_wait0();
        }
        __syncthreads();
    }

    // epilogue: scale by dinv, pack to half2, one uint4 store per row-slice
#pragma unroll
    for (int i = 0; i < 8; i++) {
        int gm = m0 + ty * 8 + i;
        if (gm >= M) continue;
        float s = g_dinv[gm];
        float c0, c1, c2, c3, c4, c5, c6, c7;
        unpack2(c0, c1, acc2[i][0]);
        unpack2(c2, c3, acc2[i][1]);
        unpack2(c4, c5, acc2[i][2]);
        unpack2(c6, c7, acc2[i][3]);
        uint4 pk = make_uint4(pack_h2(c0 * s, c1 * s), pack_h2(c2 * s, c3 * s),
                              pack_h2(c4 * s, c5 * s), pack_h2(c6 * s, c7 * s));
        *(uint4*)(g_h1h + (size_t)gm * (F1 / 2) + tx * 4) = pk;
    }
}

// ---------------- Agg1 (half2 gather, fp32 accum) + fused GEMM2 --------------
__global__ void __launch_bounds__(256) k_agg1(
    const float* __restrict__ b1, const float* __restrict__ W2, int n) {
    __shared__ float Wt[F2][F1];
    for (int idx = threadIdx.x; idx < (F1 * F2) / 4; idx += 256) {
        int k = idx >> 2;
        int q4 = (idx & 3) * 4;
        float4 v = *(const float4*)(W2 + (size_t)k * F2 + q4);
        Wt[q4 + 0][k] = v.x;
        Wt[q4 + 1][k] = v.y;
        Wt[q4 + 2][k] = v.z;
        Wt[q4 + 3][k] = v.w;
    }
    __syncthreads();

    int warp = (blockIdx.x * blockDim.x + threadIdx.x) >> 5;
    int lane = threadIdx.x & 31;
    if (warp >= n) return;
    int i = warp;
    int beg = g_rowptr[i], end = g_rowptr[i + 1];
    const unsigned* hs = g_h1h;
    // lane covers dims lane*4..lane*4+3 -> uint2 at uint index row*64 + lane*2
    float4 acc0, acc1 = make_float4(0.f, 0.f, 0.f, 0.f);
    {
        uint2 u = *(const uint2*)(hs + (size_t)i * (F1 / 2) + lane * 2);
        float2 a = __half22float2(*(__half2*)&u.x);
        float2 b = __half22float2(*(__half2*)&u.y);
        acc0 = make_float4(a.x, a.y, b.x, b.y);
    }
    for (int e = beg; e < end; e += 32) {
        int cnt = min(32, end - e);
        int j = (e + lane < end) ? g_csr[e + lane] : 0;
        int t = 0;
        for (; t + 1 < cnt; t += 2) {
            int j0 = __shfl_sync(0xffffffffu, j, t);
            int j1 = __shfl_sync(0xffffffffu, j, t + 1);
            uint2 u0 = *(const uint2*)(hs + (size_t)j0 * (F1 / 2) + lane * 2);
            uint2 u1 = *(const uint2*)(hs + (size_t)j1 * (F1 / 2) + lane * 2);
            float2 a0 = __half22float2(*(__half2*)&u0.x);
            float2 b0 = __half22float2(*(__half2*)&u0.y);
            float2 a1 = __half22float2(*(__half2*)&u1.x);
            float2 b1 = __half22float2(*(__half2*)&u1.y);
            acc0.x += a0.x; acc0.y += a0.y; acc0.z += b0.x; acc0.w += b0.y;
            acc1.x += a1.x; acc1.y += a1.y; acc1.z += b1.x; acc1.w += b1.y;
        }
        if (t < cnt) {
            int j0 = __shfl_sync(0xffffffffu, j, t);
            uint2 u0 = *(const uint2*)(hs + (size_t)j0 * (F1 / 2) + lane * 2);
            float2 a0 = __half22float2(*(__half2*)&u0.x);
            float2 b0 = __half22float2(*(__half2*)&u0.y);
            acc0.x += a0.x; acc0.y += a0.y; acc0.z += b0.x; acc0.w += b0.y;
        }
    }
    float s = g_dinv[i];
    float4 bb = *(const float4*)(b1 + lane * 4);
    float f[4];
    f[0] = fmaxf(fmaf(acc0.x + acc1.x, s, bb.x), 0.f);
    f[1] = fmaxf(fmaf(acc0.y + acc1.y, s, bb.y), 0.f);
    f[2] = fmaxf(fmaf(acc0.z + acc1.z, s, bb.z), 0.f);
    f[3] = fmaxf(fmaf(acc0.w + acc1.w, s, bb.w), 0.f);

    float p[F2];
#pragma unroll
    for (int q = 0; q < F2; q++) {
        float4 w = *(const float4*)(&Wt[q][lane * 4]);
        p[q] = f[0] * w.x + f[1] * w.y + f[2] * w.z + f[3] * w.w;
    }
#pragma unroll
    for (int d = 16; d >= 1; d >>= 1) {
#pragma unroll
        for (int q = 0; q < F2; q++)
            p[q] += __shfl_xor_sync(0xffffffffu, p[q], d);
    }
    if (lane < 4) {
        float4 v = make_float4(p[lane * 4] * s, p[lane * 4 + 1] * s,
                               p[lane * 4 + 2] * s, p[lane * 4 + 3] * s);
        *(float4*)(g_h2 + (size_t)i * F2 + lane * 4) = v;
    }
}

// ---------------- Agg2: 4 threads per node, 16 dims, + b2 -------------------
__global__ void k_agg2(const float* __restrict__ b2, float* __restrict__ out, int n) {
    int gt = blockIdx.x * blockDim.x + threadIdx.x;
    int i = gt >> 2;
    if (i >= n) return;
    int q = (gt & 3) * 4;
    int beg = g_rowptr[i], end = g_rowptr[i + 1];
    const float* hs = g_h2;
    float4 acc = *(const float4*)(hs + (size_t)i * F2 + q);
    for (int e = beg; e < end; e++) {
        int j = g_csr[e];
        float4 v = *(const float4*)(hs + (size_t)j * F2 + q);
        acc.x += v.x; acc.y += v.y; acc.z += v.z; acc.w += v.w;
    }
    float s = g_dinv[i];
    float4 bb = *(const float4*)(b2 + q);
    float4 r = make_float4(fmaf(acc.x, s, bb.x), fmaf(acc.y, s, bb.y),
                           fmaf(acc.z, s, bb.z), fmaf(acc.w, s, bb.w));
    *(float4*)(out + (size_t)i * F2 + q) = r;
}

// ---------------- launch: fork/join graph ------------------------------------
extern "C" void kernel_launch(void* const* d_in, const int* in_sizes, int n_in,
                              void* d_out, int out_size) {
    const float* x  = (const float*)d_in[0];
    const int*   ei = (const int*)d_in[1];
    const float* W1 = (const float*)d_in[2];
    const float* b1 = (const float*)d_in[3];
    const float* W2 = (const float*)d_in[4];
    const float* b2 = (const float*)d_in[5];
    float* out = (float*)d_out;

    int n = in_sizes[0] / F0;       // 100000
    int E = in_sizes[1] / 2;        // 1600000

    static cudaStream_t s2 = 0;
    static cudaEvent_t evFork = 0, evJoin = 0;
    if (!s2) {
        cudaStreamCreateWithFlags(&s2, cudaStreamNonBlocking);
        cudaEventCreateWithFlags(&evFork, cudaEventDisableTiming);
        cudaEventCreateWithFlags(&evJoin, cudaEventDisableTiming);
    }

    int tb = 256;
    k_zero<<<(n + tb - 1) / tb, tb>>>(n);
    k_deg<<<(E + tb - 1) / tb, tb>>>(ei, E, n);

    cudaEventRecord(evFork, 0);
    cudaStreamWaitEvent(s2, evFork, 0);

    k_dinv<<<(n + tb - 1) / tb, tb>>>(n);
    k_gemm1<<<(n + 127) / 128, 256>>>(x, W1, n);

    int nb = (n + 4095) / 4096;
    k_scan1<<<nb, 256, 0, s2>>>(n);
    k_scan2<<<1, 32, 0, s2>>>(nb);
    k_scan3<<<(n + tb - 1) / tb, tb, 0, s2>>>(n, E);
    k_fill<<<(E + tb - 1) / tb, tb, 0, s2>>>(ei, E, n);
    cudaEventRecord(evJoin, s2);

    cudaStreamWaitEvent(0, evJoin, 0);
    k_agg1<<<(n * 32 + tb - 1) / tb, tb>>>(b1, W2, n);
    k_agg2<<<(n * 4 + tb - 1) / tb, tb>>>(b2, out, n);
}

// round 11
// speedup vs baseline: 2.6878x; 1.1280x over previous
#include <cuda_runtime.h>
#include <cuda_bf16.h>
#include <cuda_fp16.h>
#include <math.h>
#include <cstdint>

#define N_MAX 100000
#define E_MAX 1600000
#define F0 256
#define F1 128
#define F2 16

// ---------------- scratch (static device globals; no allocation) ------------
__device__ int      g_deg[N_MAX];
__device__ float    g_dinv[N_MAX];
__device__ int      g_rowptr[N_MAX + 1];
__device__ int      g_cursor[N_MAX];
__device__ int      g_csr[E_MAX];
__device__ unsigned g_h1h[(size_t)N_MAX * F1 / 2];  // h1 as half2 pairs
__device__ float    g_h2[(size_t)N_MAX * F2];
__device__ int      g_bsums[64];
// W1 split to bf16 hi/lo, transposed to [n][k] (128 rows x 256 k = 128 uints/row)
__device__ uint32_t g_Wh[128 * 128];
__device__ uint32_t g_Wl[128 * 128];

// ---------------- helpers ----------------------------------------------------
__device__ __forceinline__ unsigned smem_u32(const void* p) {
    unsigned r;
    asm("{ .reg .u64 t; cvta.to.shared.u64 t, %1; cvt.u32.u64 %0, t; }"
        : "=r"(r) : "l"(p));
    return r;
}
__device__ __forceinline__ void cp_async16(unsigned dst, const void* src) {
    asm volatile("cp.async.ca.shared.global [%0], [%1], 16;"
                 :: "r"(dst), "l"(src));
}
__device__ __forceinline__ void cp_commit() { asm volatile("cp.async.commit_group;"); }
__device__ __forceinline__ void cp_wait0()  { asm volatile("cp.async.wait_group 0;"); }
__device__ __forceinline__ unsigned pack_h2(float a, float b) {
    __half2 h = __floats2half2_rn(a, b);
    return *(unsigned*)&h;
}
__device__ __forceinline__ void ldmx4(uint32_t* r, unsigned addr) {
    asm volatile("ldmatrix.sync.aligned.m8n8.x4.shared.b16 {%0,%1,%2,%3}, [%4];"
                 : "=r"(r[0]), "=r"(r[1]), "=r"(r[2]), "=r"(r[3]) : "r"(addr));
}
__device__ __forceinline__ void ldmx2(uint32_t* r, unsigned addr) {
    asm volatile("ldmatrix.sync.aligned.m8n8.x2.shared.b16 {%0,%1}, [%2];"
                 : "=r"(r[0]), "=r"(r[1]) : "r"(addr));
}
__device__ __forceinline__ void mma_bf16(float* d, const uint32_t* a, const uint32_t* b) {
    asm volatile(
        "mma.sync.aligned.m16n8k16.row.col.f32.bf16.bf16.f32 "
        "{%0,%1,%2,%3}, {%4,%5,%6,%7}, {%8,%9}, {%0,%1,%2,%3};"
        : "+f"(d[0]), "+f"(d[1]), "+f"(d[2]), "+f"(d[3])
        : "r"(a[0]), "r"(a[1]), "r"(a[2]), "r"(a[3]), "r"(b[0]), "r"(b[1]));
}
__device__ __forceinline__ uint32_t bfpair(float a, float b) {
    union { __nv_bfloat162 v; uint32_t u; } u;
    u.v = __nv_bfloat162(__float2bfloat16(a), __float2bfloat16(b));
    return u.u;
}

// ---------------- small kernels ----------------------------------------------
__global__ void k_zero(int n) {
    int i = blockIdx.x * blockDim.x + threadIdx.x;
    if (i < n) g_deg[i] = 0;
}
__global__ void k_deg(const int* __restrict__ ei, int E, int n) {
    int i = blockIdx.x * blockDim.x + threadIdx.x;
    if (i < E) {
        int dst = ei[E + i];
        if ((unsigned)dst < (unsigned)n) atomicAdd(&g_deg[dst], 1);
    }
}
__global__ void k_dinv(int n) {
    int i = blockIdx.x * blockDim.x + threadIdx.x;
    if (i < n) g_dinv[i] = rsqrtf((float)(g_deg[i] + 1));
}

// W1 [256][128] fp32 -> g_Wh/g_Wl [n][k] bf16 split
__global__ void k_prepw(const float* __restrict__ W) {
    int idx = blockIdx.x * blockDim.x + threadIdx.x;
    if (idx >= 128 * 32) return;
    int nn = idx >> 5;
    int kg = idx & 31;          // 8 k's at kg*8
    uint32_t hu[4], lu[4];
#pragma unroll
    for (int p = 0; p < 4; p++) {
        float v0 = W[(size_t)(kg * 8 + 2 * p) * F1 + nn];
        float v1 = W[(size_t)(kg * 8 + 2 * p + 1) * F1 + nn];
        __nv_bfloat16 h0 = __float2bfloat16(v0);
        __nv_bfloat16 h1 = __float2bfloat16(v1);
        float l0 = v0 - __bfloat162float(h0);
        float l1 = v1 - __bfloat162float(h1);
        hu[p] = bfpair(__bfloat162float(h0), __bfloat162float(h1));
        lu[p] = bfpair(l0, l1);
    }
    *(uint4*)(g_Wh + nn * 128 + kg * 4) = make_uint4(hu[0], hu[1], hu[2], hu[3]);
    *(uint4*)(g_Wl + nn * 128 + kg * 4) = make_uint4(lu[0], lu[1], lu[2], lu[3]);
}

// ---------------- scan + CSR -------------------------------------------------
__global__ void k_scan1(int n) {
    __shared__ int warpsum[8];
    int base = blockIdx.x * 4096;
    int t0 = base + threadIdx.x * 16;
    int vals[16];
    int s = 0;
#pragma unroll
    for (int j = 0; j < 16; j++) {
        int idx = t0 + j;
        int v = (idx < n) ? g_deg[idx] : 0;
        vals[j] = s;
        s += v;
    }
    int lane = threadIdx.x & 31, w = threadIdx.x >> 5;
    int x = s;
#pragma unroll
    for (int d = 1; d < 32; d <<= 1) {
        int y = __shfl_up_sync(0xffffffffu, x, d);
        if (lane >= d) x += y;
    }
    if (lane == 31) warpsum[w] = x;
    __syncthreads();
    if (w == 0 && lane < 8) {
        int y = warpsum[lane];
#pragma unroll
        for (int d = 1; d < 8; d <<= 1) {
            int z = __shfl_up_sync(0xffu, y, d);
            if (lane >= d) y += z;
        }
        warpsum[lane] = y;
    }
    __syncthreads();
    int warpoff = (w > 0) ? warpsum[w - 1] : 0;
    int throff = warpoff + x - s;
#pragma unroll
    for (int j = 0; j < 16; j++) {
        int idx = t0 + j;
        if (idx < n) g_rowptr[idx] = throff + vals[j];
    }
    if (threadIdx.x == 255) g_bsums[blockIdx.x] = warpoff + x;
}
__global__ void k_scan2(int nb) {
    if (threadIdx.x == 0 && blockIdx.x == 0) {
        int s = 0;
        for (int i = 0; i < nb; i++) { int v = g_bsums[i]; g_bsums[i] = s; s += v; }
    }
}
__global__ void k_scan3(int n, int E) {
    int i = blockIdx.x * blockDim.x + threadIdx.x;
    if (i < n) {
        int r = g_rowptr[i] + g_bsums[i >> 12];
        g_rowptr[i] = r;
        g_cursor[i] = r;
    }
    if (i == 0) g_rowptr[n] = E;
}
__global__ void k_fill(const int* __restrict__ ei, int E, int n) {
    int i = blockIdx.x * blockDim.x + threadIdx.x;
    if (i < E) {
        int dst = ei[E + i];
        int src = ei[i];
        if ((unsigned)dst < (unsigned)n && (unsigned)src < (unsigned)n) {
            int pos = atomicAdd(&g_cursor[dst], 1);
            g_csr[pos] = src;
        }
    }
}

// ---------------- GEMM1 via mma.sync bf16 3-split ---------------------------
// CTA 128x128, K=256 in 16 chunks of k16. B ([n][k] hi/lo bf16) resident in
// smem (528B padded rows, conflict-free ldmatrix). A converted inline, 48B
// padded rows, double buffered. 8 warps as 2(m)x4(n); warp tile m64 x n32.
#define BS_ROW 528
#define BSZ    67584          /* 128*528 */
#define A_ROW  48
#define ASZ    6144           /* 128*48 */
#define SM_TOTAL (2*BSZ + 2*2*ASZ)   /* 159744 */

__global__ void __launch_bounds__(256) k_gemm1(const float* __restrict__ X, int M) {
    extern __shared__ char sm[];
    unsigned sb = smem_u32(sm);
    const unsigned BsH = sb, BsL = sb + BSZ, Ab = sb + 2 * BSZ;

    int tid = threadIdx.x, lane = tid & 31, wid = tid >> 5;
    int wm = wid >> 2, wn = wid & 3;
    int m0 = blockIdx.x * 128;

    // load resident B (hi+lo): 8192 x 16B
    for (int q = tid; q < 8192; q += 256) {
        int mi = q >> 12;
        int r  = (q >> 5) & 127;
        int c  = q & 31;
        unsigned dst = (mi ? BsL : BsH) + r * BS_ROW + c * 16;
        const uint32_t* src = (mi ? g_Wl : g_Wh) + r * 128 + c * 4;
        cp_async16(dst, src);
    }
    cp_commit();

    float acc[4][4][4];
#pragma unroll
    for (int i = 0; i < 4; i++)
#pragma unroll
        for (int j = 0; j < 4; j++)
#pragma unroll
            for (int q = 0; q < 4; q++) acc[i][j][q] = 0.f;

    int mrow = tid >> 1, khalf = tid & 1;
    int gm = m0 + mrow;
    bool ok = gm < M;
    const float4 z4 = make_float4(0.f, 0.f, 0.f, 0.f);
    const float* xrow = X + (size_t)gm * F0 + khalf * 8;

    // stage chunk 0 into buffer 0
    {
        float4 va = ok ? *(const float4*)(xrow)     : z4;
        float4 vb = ok ? *(const float4*)(xrow + 4) : z4;
        float vf[8] = {va.x, va.y, va.z, va.w, vb.x, vb.y, vb.z, vb.w};
        uint32_t hu[4], lu[4];
#pragma unroll
        for (int p = 0; p < 4; p++) {
            float a = vf[2 * p], b = vf[2 * p + 1];
            __nv_bfloat16 ha = __float2bfloat16(a), hb = __float2bfloat16(b);
            hu[p] = bfpair(__bfloat162float(ha), __bfloat162float(hb));
            lu[p] = bfpair(a - __bfloat162float(ha), b - __bfloat162float(hb));
        }
        size_t off = (size_t)(2 * BSZ) + mrow * A_ROW + khalf * 16;
        *(uint4*)(sm + off)       = make_uint4(hu[0], hu[1], hu[2], hu[3]);
        *(uint4*)(sm + off + ASZ) = make_uint4(lu[0], lu[1], lu[2], lu[3]);
    }
    cp_wait0();
    __syncthreads();

    int arow = (lane & 7) + ((lane >> 3) & 1) * 8;
    int acol = ((lane >> 4) & 1) * 16;
    int brow = lane & 7;
    int bsel = ((lane >> 3) & 1) * 16;

#pragma unroll 1
    for (int it = 0; it < 16; it++) {
        int cur = it & 1;
        float4 na = z4, nb = z4;
        if (it < 15) {
            const float* xc = xrow + (it + 1) * 16;
            na = ok ? *(const float4*)(xc)     : z4;
            nb = ok ? *(const float4*)(xc + 4) : z4;
        }
        unsigned AhB = Ab + cur * 2 * ASZ, AlB = AhB + ASZ;
        uint32_t ah[4][4], al[4][4], bh[4][2], bl[4][2];
#pragma unroll
        for (int ti = 0; ti < 4; ti++) {
            unsigned o = (wm * 64 + ti * 16 + arow) * A_ROW + acol;
            ldmx4(ah[ti], AhB + o);
            ldmx4(al[ti], AlB + o);
        }
#pragma unroll
        for (int tj = 0; tj < 4; tj++) {
            unsigned o = (wn * 32 + tj * 8 + brow) * BS_ROW + it * 32 + bsel;
            ldmx2(bh[tj], BsH + o);
            ldmx2(bl[tj], BsL + o);
        }
#pragma unroll
        for (int ti = 0; ti < 4; ti++)
#pragma unroll
            for (int tj = 0; tj < 4; tj++) {
                mma_bf16(acc[ti][tj], ah[ti], bh[tj]);
                mma_bf16(acc[ti][tj], ah[ti], bl[tj]);
                mma_bf16(acc[ti][tj], al[ti], bh[tj]);
            }
        if (it < 15) {
            float vf[8] = {na.x, na.y, na.z, na.w, nb.x, nb.y, nb.z, nb.w};
            uint32_t hu[4], lu[4];
#pragma unroll
            for (int p = 0; p < 4; p++) {
                float a = vf[2 * p], b = vf[2 * p + 1];
                __nv_bfloat16 ha = __float2bfloat16(a), hb = __float2bfloat16(b);
                hu[p] = bfpair(__bfloat162float(ha), __bfloat162float(hb));
                lu[p] = bfpair(a - __bfloat162float(ha), b - __bfloat162float(hb));
            }
            size_t off = (size_t)(2 * BSZ) + (cur ^ 1) * 2 * ASZ + mrow * A_ROW + khalf * 16;
            *(uint4*)(sm + off)       = make_uint4(hu[0], hu[1], hu[2], hu[3]);
            *(uint4*)(sm + off + ASZ) = make_uint4(lu[0], lu[1], lu[2], lu[3]);
        }
        __syncthreads();
    }

    // epilogue: d0/d1 -> row m, cols n,n+1 ; d2/d3 -> row m+8
#pragma unroll
    for (int ti = 0; ti < 4; ti++) {
#pragma unroll
        for (int tj = 0; tj < 4; tj++) {
            int mA = wm * 64 + ti * 16 + (lane >> 2);
            int nn = wn * 32 + tj * 8 + (lane & 3) * 2;
            int r0 = m0 + mA, r1 = r0 + 8;
            if (r0 < M) {
                float s = g_dinv[r0];
                g_h1h[(size_t)r0 * 64 + (nn >> 1)] =
                    pack_h2(acc[ti][tj][0] * s, acc[ti][tj][1] * s);
            }
            if (r1 < M) {
                float s = g_dinv[r1];
                g_h1h[(size_t)r1 * 64 + (nn >> 1)] =
                    pack_h2(acc[ti][tj][2] * s, acc[ti][tj][3] * s);
            }
        }
    }
}

// ---------------- Agg1 (half2 gather, fp32 accum) + fused GEMM2 --------------
__global__ void __launch_bounds__(256) k_agg1(
    const float* __restrict__ b1, const float* __restrict__ W2, int n) {
    __shared__ float Wt[F2][F1];
    for (int idx = threadIdx.x; idx < (F1 * F2) / 4; idx += 256) {
        int k = idx >> 2;
        int q4 = (idx & 3) * 4;
        float4 v = *(const float4*)(W2 + (size_t)k * F2 + q4);
        Wt[q4 + 0][k] = v.x;
        Wt[q4 + 1][k] = v.y;
        Wt[q4 + 2][k] = v.z;
        Wt[q4 + 3][k] = v.w;
    }
    __syncthreads();

    int warp = (blockIdx.x * blockDim.x + threadIdx.x) >> 5;
    int lane = threadIdx.x & 31;
    if (warp >= n) return;
    int i = warp;
    int beg = g_rowptr[i], end = g_rowptr[i + 1];
    const unsigned* hs = g_h1h;
    float4 acc0, acc1 = make_float4(0.f, 0.f, 0.f, 0.f);
    {
        uint2 u = *(const uint2*)(hs + (size_t)i * (F1 / 2) + lane * 2);
        float2 a = __half22float2(*(__half2*)&u.x);
        float2 b = __half22float2(*(__half2*)&u.y);
        acc0 = make_float4(a.x, a.y, b.x, b.y);
    }
    for (int e = beg; e < end; e += 32) {
        int cnt = min(32, end - e);
        int j = (e + lane < end) ? g_csr[e + lane] : 0;
        int t = 0;
        for (; t + 1 < cnt; t += 2) {
            int j0 = __shfl_sync(0xffffffffu, j, t);
            int j1 = __shfl_sync(0xffffffffu, j, t + 1);
            uint2 u0 = *(const uint2*)(hs + (size_t)j0 * (F1 / 2) + lane * 2);
            uint2 u1 = *(const uint2*)(hs + (size_t)j1 * (F1 / 2) + lane * 2);
            float2 a0 = __half22float2(*(__half2*)&u0.x);
            float2 b0 = __half22float2(*(__half2*)&u0.y);
            float2 a1 = __half22float2(*(__half2*)&u1.x);
            float2 b1 = __half22float2(*(__half2*)&u1.y);
            acc0.x += a0.x; acc0.y += a0.y; acc0.z += b0.x; acc0.w += b0.y;
            acc1.x += a1.x; acc1.y += a1.y; acc1.z += b1.x; acc1.w += b1.y;
        }
        if (t < cnt) {
            int j0 = __shfl_sync(0xffffffffu, j, t);
            uint2 u0 = *(const uint2*)(hs + (size_t)j0 * (F1 / 2) + lane * 2);
            float2 a0 = __half22float2(*(__half2*)&u0.x);
            float2 b0 = __half22float2(*(__half2*)&u0.y);
            acc0.x += a0.x; acc0.y += a0.y; acc0.z += b0.x; acc0.w += b0.y;
        }
    }
    float s = g_dinv[i];
    float4 bb = *(const float4*)(b1 + lane * 4);
    float f[4];
    f[0] = fmaxf(fmaf(acc0.x + acc1.x, s, bb.x), 0.f);
    f[1] = fmaxf(fmaf(acc0.y + acc1.y, s, bb.y), 0.f);
    f[2] = fmaxf(fmaf(acc0.z + acc1.z, s, bb.z), 0.f);
    f[3] = fmaxf(fmaf(acc0.w + acc1.w, s, bb.w), 0.f);

    float p[F2];
#pragma unroll
    for (int q = 0; q < F2; q++) {
        float4 w = *(const float4*)(&Wt[q][lane * 4]);
        p[q] = f[0] * w.x + f[1] * w.y + f[2] * w.z + f[3] * w.w;
    }
#pragma unroll
    for (int d = 16; d >= 1; d >>= 1) {
#pragma unroll
        for (int q = 0; q < F2; q++)
            p[q] += __shfl_xor_sync(0xffffffffu, p[q], d);
    }
    if (lane < 4) {
        float4 v = make_float4(p[lane * 4] * s, p[lane * 4 + 1] * s,
                               p[lane * 4 + 2] * s, p[lane * 4 + 3] * s);
        *(float4*)(g_h2 + (size_t)i * F2 + lane * 4) = v;
    }
}

// ---------------- Agg2: 4 threads per node, 16 dims, + b2 -------------------
__global__ void k_agg2(const float* __restrict__ b2, float* __restrict__ out, int n) {
    int gt = blockIdx.x * blockDim.x + threadIdx.x;
    int i = gt >> 2;
    if (i >= n) return;
    int q = (gt & 3) * 4;
    int beg = g_rowptr[i], end = g_rowptr[i + 1];
    const float* hs = g_h2;
    float4 acc = *(const float4*)(hs + (size_t)i * F2 + q);
    for (int e = beg; e < end; e++) {
        int j = g_csr[e];
        float4 v = *(const float4*)(hs + (size_t)j * F2 + q);
        acc.x += v.x; acc.y += v.y; acc.z += v.z; acc.w += v.w;
    }
    float s = g_dinv[i];
    float4 bb = *(const float4*)(b2 + q);
    float4 r = make_float4(fmaf(acc.x, s, bb.x), fmaf(acc.y, s, bb.y),
                           fmaf(acc.z, s, bb.z), fmaf(acc.w, s, bb.w));
    *(float4*)(out + (size_t)i * F2 + q) = r;
}

// ---------------- launch: fork/join graph ------------------------------------
extern "C" void kernel_launch(void* const* d_in, const int* in_sizes, int n_in,
                              void* d_out, int out_size) {
    const float* x  = (const float*)d_in[0];
    const int*   ei = (const int*)d_in[1];
    const float* W1 = (const float*)d_in[2];
    const float* b1 = (const float*)d_in[3];
    const float* W2 = (const float*)d_in[4];
    const float* b2 = (const float*)d_in[5];
    float* out = (float*)d_out;

    int n = in_sizes[0] / F0;       // 100000
    int E = in_sizes[1] / 2;        // 1600000

    static cudaStream_t s2 = 0;
    static cudaEvent_t evFork = 0, evJoin = 0;
    if (!s2) {
        cudaStreamCreateWithFlags(&s2, cudaStreamNonBlocking);
        cudaEventCreateWithFlags(&evFork, cudaEventDisableTiming);
        cudaEventCreateWithFlags(&evJoin, cudaEventDisableTiming);
        cudaFuncSetAttribute(k_gemm1, cudaFuncAttributeMaxDynamicSharedMemorySize,
                             SM_TOTAL);
    }

    int tb = 256;
    k_prepw<<<16, 256>>>(W1);
    k_zero<<<(n + tb - 1) / tb, tb>>>(n);
    k_deg<<<(E + tb - 1) / tb, tb>>>(ei, E, n);

    cudaEventRecord(evFork, 0);
    cudaStreamWaitEvent(s2, evFork, 0);

    k_dinv<<<(n + tb - 1) / tb, tb>>>(n);
    k_gemm1<<<(n + 127) / 128, 256, SM_TOTAL>>>(x, n);

    int nb = (n + 4095) / 4096;
    k_scan1<<<nb, 256, 0, s2>>>(n);
    k_scan2<<<1, 32, 0, s2>>>(nb);
    k_scan3<<<(n + tb - 1) / tb, tb, 0, s2>>>(n, E);
    k_fill<<<(E + tb - 1) / tb, tb, 0, s2>>>(ei, E, n);
    cudaEventRecord(evJoin, s2);

    cudaStreamWaitEvent(0, evJoin, 0);
    k_agg1<<<(n * 32 + tb - 1) / tb, tb>>>(b1, W2, n);
    k_agg2<<<(n * 4 + tb - 1) / tb, tb>>>(b2, out, n);
}

// round 12
// speedup vs baseline: 3.1039x; 1.1548x over previous
#include <cuda_runtime.h>
#include <cuda_bf16.h>
#include <cuda_fp16.h>
#include <math.h>
#include <cstdint>

#define N_MAX 100000
#define E_MAX 1600000
#define F0 256
#define F1 128
#define F2 16

// ---------------- scratch (static device globals; no allocation) ------------
__device__ int      g_deg[N_MAX];
__device__ int      g_rowptr[N_MAX + 1];
__device__ int      g_cursor[N_MAX];
__device__ int      g_csr[E_MAX];
__device__ unsigned g_h1h[(size_t)N_MAX * F1 / 2];  // h1 as half2 pairs
__device__ float    g_h2[(size_t)N_MAX * F2];
__device__ int      g_bsums[64];
// W1 split bf16 hi/lo, chunked [16 kchunks][128 n][8 uints (16 k bf16)]
__device__ uint32_t g_Wh[16 * 128 * 8];
__device__ uint32_t g_Wl[16 * 128 * 8];

// ---------------- helpers ----------------------------------------------------
__device__ __forceinline__ unsigned smem_u32(const void* p) {
    unsigned r;
    asm("{ .reg .u64 t; cvta.to.shared.u64 t, %1; cvt.u32.u64 %0, t; }"
        : "=r"(r) : "l"(p));
    return r;
}
__device__ __forceinline__ void cp_async16(unsigned dst, const void* src) {
    asm volatile("cp.async.ca.shared.global [%0], [%1], 16;"
                 :: "r"(dst), "l"(src));
}
__device__ __forceinline__ void cp_commit() { asm volatile("cp.async.commit_group;"); }
__device__ __forceinline__ void cp_wait0()  { asm volatile("cp.async.wait_group 0;"); }
__device__ __forceinline__ unsigned pack_h2(float a, float b) {
    __half2 h = __floats2half2_rn(a, b);
    return *(unsigned*)&h;
}
__device__ __forceinline__ void ldmx4(uint32_t* r, unsigned addr) {
    asm volatile("ldmatrix.sync.aligned.m8n8.x4.shared.b16 {%0,%1,%2,%3}, [%4];"
                 : "=r"(r[0]), "=r"(r[1]), "=r"(r[2]), "=r"(r[3]) : "r"(addr));
}
__device__ __forceinline__ void ldmx2(uint32_t* r, unsigned addr) {
    asm volatile("ldmatrix.sync.aligned.m8n8.x2.shared.b16 {%0,%1}, [%2];"
                 : "=r"(r[0]), "=r"(r[1]) : "r"(addr));
}
__device__ __forceinline__ void mma_bf16(float* d, const uint32_t* a, const uint32_t* b) {
    asm volatile(
        "mma.sync.aligned.m16n8k16.row.col.f32.bf16.bf16.f32 "
        "{%0,%1,%2,%3}, {%4,%5,%6,%7}, {%8,%9}, {%0,%1,%2,%3};"
        : "+f"(d[0]), "+f"(d[1]), "+f"(d[2]), "+f"(d[3])
        : "r"(a[0]), "r"(a[1]), "r"(a[2]), "r"(a[3]), "r"(b[0]), "r"(b[1]));
}
__device__ __forceinline__ uint32_t bfpair(float a, float b) {
    union { __nv_bfloat162 v; uint32_t u; } u;
    u.v = __nv_bfloat162(__float2bfloat16(a), __float2bfloat16(b));
    return u.u;
}
__device__ __forceinline__ float dinv_of(int i) {
    return rsqrtf((float)(g_deg[i] + 1));
}

// ---------------- small kernels ----------------------------------------------
__global__ void k_zero(int n) {
    int i = blockIdx.x * blockDim.x + threadIdx.x;
    if (i < n) g_deg[i] = 0;
}
__global__ void k_deg(const int* __restrict__ ei, int E, int n) {
    int i = blockIdx.x * blockDim.x + threadIdx.x;
    if (i < E) {
        int dst = ei[E + i];
        if ((unsigned)dst < (unsigned)n) atomicAdd(&g_deg[dst], 1);
    }
}

// W1 [256][128] fp32 -> chunked hi/lo bf16 [c][n][8u]
__global__ void k_prepw(const float* __restrict__ W) {
    int idx = blockIdx.x * blockDim.x + threadIdx.x;
    if (idx >= 16 * 128) return;
    int c = idx >> 7;
    int nn = idx & 127;
    uint32_t hu[8], lu[8];
#pragma unroll
    for (int p = 0; p < 8; p++) {
        float v0 = W[(size_t)(c * 16 + 2 * p) * F1 + nn];
        float v1 = W[(size_t)(c * 16 + 2 * p + 1) * F1 + nn];
        __nv_bfloat16 h0 = __float2bfloat16(v0);
        __nv_bfloat16 h1 = __float2bfloat16(v1);
        hu[p] = bfpair(__bfloat162float(h0), __bfloat162float(h1));
        lu[p] = bfpair(v0 - __bfloat162float(h0), v1 - __bfloat162float(h1));
    }
    uint32_t* dh = g_Wh + (size_t)idx * 8;
    uint32_t* dl = g_Wl + (size_t)idx * 8;
    *(uint4*)(dh)     = make_uint4(hu[0], hu[1], hu[2], hu[3]);
    *(uint4*)(dh + 4) = make_uint4(hu[4], hu[5], hu[6], hu[7]);
    *(uint4*)(dl)     = make_uint4(lu[0], lu[1], lu[2], lu[3]);
    *(uint4*)(dl + 4) = make_uint4(lu[4], lu[5], lu[6], lu[7]);
}

// ---------------- scan + CSR -------------------------------------------------
__global__ void k_scan1(int n) {
    __shared__ int warpsum[8];
    int base = blockIdx.x * 4096;
    int t0 = base + threadIdx.x * 16;
    int vals[16];
    int s = 0;
#pragma unroll
    for (int j = 0; j < 16; j++) {
        int idx = t0 + j;
        int v = (idx < n) ? g_deg[idx] : 0;
        vals[j] = s;
        s += v;
    }
    int lane = threadIdx.x & 31, w = threadIdx.x >> 5;
    int x = s;
#pragma unroll
    for (int d = 1; d < 32; d <<= 1) {
        int y = __shfl_up_sync(0xffffffffu, x, d);
        if (lane >= d) x += y;
    }
    if (lane == 31) warpsum[w] = x;
    __syncthreads();
    if (w == 0 && lane < 8) {
        int y = warpsum[lane];
#pragma unroll
        for (int d = 1; d < 8; d <<= 1) {
            int z = __shfl_up_sync(0xffu, y, d);
            if (lane >= d) y += z;
        }
        warpsum[lane] = y;
    }
    __syncthreads();
    int warpoff = (w > 0) ? warpsum[w - 1] : 0;
    int throff = warpoff + x - s;
#pragma unroll
    for (int j = 0; j < 16; j++) {
        int idx = t0 + j;
        if (idx < n) g_rowptr[idx] = throff + vals[j];
    }
    if (threadIdx.x == 255) g_bsums[blockIdx.x] = warpoff + x;
}
__global__ void k_scan2(int nb) {
    if (threadIdx.x == 0 && blockIdx.x == 0) {
        int s = 0;
        for (int i = 0; i < nb; i++) { int v = g_bsums[i]; g_bsums[i] = s; s += v; }
    }
}
__global__ void k_scan3(int n, int E) {
    int i = blockIdx.x * blockDim.x + threadIdx.x;
    if (i < n) {
        int r = g_rowptr[i] + g_bsums[i >> 12];
        g_rowptr[i] = r;
        g_cursor[i] = r;
    }
    if (i == 0) g_rowptr[n] = E;
}
__global__ void k_fill(const int* __restrict__ ei, int E, int n) {
    int i = blockIdx.x * blockDim.x + threadIdx.x;
    if (i < E) {
        int dst = ei[E + i];
        int src = ei[i];
        if ((unsigned)dst < (unsigned)n && (unsigned)src < (unsigned)n) {
            int pos = atomicAdd(&g_cursor[dst], 1);
            g_csr[pos] = src;
        }
    }
}

// ---------------- GEMM1 via mma.sync bf16 3-split, streamed B ----------------
// CTA 128x128, 16 k16-chunks. B chunk tiles (hi/lo, 48B-padded rows) streamed
// via double-buffered cp.async; A converted inline + STS double-buffered.
// smem 48KB -> 4 CTAs/SM. 8 warps as 2(m)x4(n), warp tile m64 x n32.
#define A_ROW  48
#define ASZ    6144                 /* 128 rows * 48B */
#define B_ROW  48
#define BCH    6144                 /* 128 rows * 48B per chunk buffer */
#define SM_TOTAL (4*BCH + 4*ASZ)    /* BsH[2]+BsL[2] + Ah[2]+Al[2] = 49152 */

__global__ void __launch_bounds__(256) k_gemm1(const float* __restrict__ X, int M) {
    extern __shared__ char sm[];
    unsigned sb = smem_u32(sm);
    // layout: BsH0, BsH1, BsL0, BsL1, Ah0, Ah1, Al0, Al1 (each 6144)
    const unsigned BsH = sb, BsL = sb + 2 * BCH, Ah = sb + 4 * BCH, Al = Ah + 2 * ASZ;

    int tid = threadIdx.x, lane = tid & 31, wid = tid >> 5;
    int wm = wid >> 2, wn = wid & 3;
    int m0 = blockIdx.x * 128;

    float acc[4][4][4];
#pragma unroll
    for (int i = 0; i < 4; i++)
#pragma unroll
        for (int j = 0; j < 4; j++)
#pragma unroll
            for (int q = 0; q < 4; q++) acc[i][j][q] = 0.f;

    int mrow = tid >> 1, khalf = tid & 1;
    int gm = m0 + mrow;
    bool ok = gm < M;
    const float4 z4 = make_float4(0.f, 0.f, 0.f, 0.f);
    const float* xrow = X + (size_t)gm * F0 + khalf * 8;

    // B cp.async mapping: thread t covers row r=t>>1, half h=t&1 (16B)
    int br = tid >> 1, bh = tid & 1;
    const uint32_t* srcH = g_Wh + (size_t)br * 8 + bh * 4;
    const uint32_t* srcL = g_Wl + (size_t)br * 8 + bh * 4;
    unsigned dstB = (unsigned)(br * B_ROW + bh * 16);

    // stage chunk 0: B via cp.async, A via conversion+STS
    cp_async16(BsH + dstB, srcH);
    cp_async16(BsL + dstB, srcL);
    cp_commit();
    {
        float4 va = ok ? *(const float4*)(xrow)     : z4;
        float4 vb = ok ? *(const float4*)(xrow + 4) : z4;
        float vf[8] = {va.x, va.y, va.z, va.w, vb.x, vb.y, vb.z, vb.w};
        uint32_t hu[4], lu[4];
#pragma unroll
        for (int p = 0; p < 4; p++) {
            float a = vf[2 * p], b = vf[2 * p + 1];
            __nv_bfloat16 ha = __float2bfloat16(a), hb = __float2bfloat16(b);
            hu[p] = bfpair(__bfloat162float(ha), __bfloat162float(hb));
            lu[p] = bfpair(a - __bfloat162float(ha), b - __bfloat162float(hb));
        }
        size_t off = (size_t)(4 * BCH) + mrow * A_ROW + khalf * 16;
        *(uint4*)(sm + off)           = make_uint4(hu[0], hu[1], hu[2], hu[3]);
        *(uint4*)(sm + off + 2 * ASZ) = make_uint4(lu[0], lu[1], lu[2], lu[3]);
    }
    cp_wait0();
    __syncthreads();

    int arow = (lane & 7) + ((lane >> 3) & 1) * 8;
    int acol = ((lane >> 4) & 1) * 16;
    int brow = lane & 7;
    int bsel = ((lane >> 3) & 1) * 16;

#pragma unroll 1
    for (int it = 0; it < 16; it++) {
        int cur = it & 1, nxt = cur ^ 1;
        float4 na = z4, nb = z4;
        if (it < 15) {
            // prefetch next B chunk + next A regs
            size_t cofs = (size_t)(it + 1) * 128 * 8;
            cp_async16(BsH + nxt * BCH + dstB, srcH + cofs);
            cp_async16(BsL + nxt * BCH + dstB, srcL + cofs);
            cp_commit();
            const float* xc = xrow + (it + 1) * 16;
            na = ok ? *(const float4*)(xc)     : z4;
            nb = ok ? *(const float4*)(xc + 4) : z4;
        }
        unsigned AhB = Ah + cur * ASZ, AlB = Al + cur * ASZ;
        unsigned BhB = BsH + cur * BCH, BlB = BsL + cur * BCH;
        uint32_t ah[4][4], al[4][4], bhf[4][2], blf[4][2];
#pragma unroll
        for (int ti = 0; ti < 4; ti++) {
            unsigned o = (wm * 64 + ti * 16 + arow) * A_ROW + acol;
            ldmx4(ah[ti], AhB + o);
            ldmx4(al[ti], AlB + o);
        }
#pragma unroll
        for (int tj = 0; tj < 4; tj++) {
            unsigned o = (wn * 32 + tj * 8 + brow) * B_ROW + bsel;
            ldmx2(bhf[tj], BhB + o);
            ldmx2(blf[tj], BlB + o);
        }
#pragma unroll
        for (int ti = 0; ti < 4; ti++)
#pragma unroll
            for (int tj = 0; tj < 4; tj++) {
                mma_bf16(acc[ti][tj], ah[ti], bhf[tj]);
                mma_bf16(acc[ti][tj], ah[ti], blf[tj]);
                mma_bf16(acc[ti][tj], al[ti], bhf[tj]);
            }
        if (it < 15) {
            float vf[8] = {na.x, na.y, na.z, na.w, nb.x, nb.y, nb.z, nb.w};
            uint32_t hu[4], lu[4];
#pragma unroll
            for (int p = 0; p < 4; p++) {
                float a = vf[2 * p], b = vf[2 * p + 1];
                __nv_bfloat16 ha = __float2bfloat16(a), hb = __float2bfloat16(b);
                hu[p] = bfpair(__bfloat162float(ha), __bfloat162float(hb));
                lu[p] = bfpair(a - __bfloat162float(ha), b - __bfloat162float(hb));
            }
            size_t off = (size_t)(4 * BCH) + nxt * ASZ + mrow * A_ROW + khalf * 16;
            *(uint4*)(sm + off)           = make_uint4(hu[0], hu[1], hu[2], hu[3]);
            *(uint4*)(sm + off + 2 * ASZ) = make_uint4(lu[0], lu[1], lu[2], lu[3]);
            cp_wait0();
        }
        __syncthreads();
    }

    // epilogue: d0/d1 -> row m cols n,n+1 ; d2/d3 -> row m+8; dinv inline
#pragma unroll
    for (int ti = 0; ti < 4; ti++) {
#pragma unroll
        for (int tj = 0; tj < 4; tj++) {
            int mA = wm * 64 + ti * 16 + (lane >> 2);
            int nn = wn * 32 + tj * 8 + (lane & 3) * 2;
            int r0 = m0 + mA, r1 = r0 + 8;
            if (r0 < M) {
                float s = dinv_of(r0);
                g_h1h[(size_t)r0 * 64 + (nn >> 1)] =
                    pack_h2(acc[ti][tj][0] * s, acc[ti][tj][1] * s);
            }
            if (r1 < M) {
                float s = dinv_of(r1);
                g_h1h[(size_t)r1 * 64 + (nn >> 1)] =
                    pack_h2(acc[ti][tj][2] * s, acc[ti][tj][3] * s);
            }
        }
    }
}

// ---------------- Agg1 (half2 gather, fp32 accum) + fused GEMM2 --------------
__global__ void __launch_bounds__(256) k_agg1(
    const float* __restrict__ b1, const float* __restrict__ W2, int n) {
    __shared__ float Wt[F2][F1];
    for (int idx = threadIdx.x; idx < (F1 * F2) / 4; idx += 256) {
        int k = idx >> 2;
        int q4 = (idx & 3) * 4;
        float4 v = *(const float4*)(W2 + (size_t)k * F2 + q4);
        Wt[q4 + 0][k] = v.x;
        Wt[q4 + 1][k] = v.y;
        Wt[q4 + 2][k] = v.z;
        Wt[q4 + 3][k] = v.w;
    }
    __syncthreads();

    int warp = (blockIdx.x * blockDim.x + threadIdx.x) >> 5;
    int lane = threadIdx.x & 31;
    if (warp >= n) return;
    int i = warp;
    int beg = g_rowptr[i], end = g_rowptr[i + 1];
    const unsigned* hs = g_h1h;
    float4 acc0, acc1 = make_float4(0.f, 0.f, 0.f, 0.f);
    {
        uint2 u = *(const uint2*)(hs + (size_t)i * (F1 / 2) + lane * 2);
        float2 a = __half22float2(*(__half2*)&u.x);
        float2 b = __half22float2(*(__half2*)&u.y);
        acc0 = make_float4(a.x, a.y, b.x, b.y);
    }
    for (int e = beg; e < end; e += 32) {
        int cnt = min(32, end - e);
        int j = (e + lane < end) ? g_csr[e + lane] : 0;
        int t = 0;
        for (; t + 1 < cnt; t += 2) {
            int j0 = __shfl_sync(0xffffffffu, j, t);
            int j1 = __shfl_sync(0xffffffffu, j, t + 1);
            uint2 u0 = *(const uint2*)(hs + (size_t)j0 * (F1 / 2) + lane * 2);
            uint2 u1 = *(const uint2*)(hs + (size_t)j1 * (F1 / 2) + lane * 2);
            float2 a0 = __half22float2(*(__half2*)&u0.x);
            float2 b0 = __half22float2(*(__half2*)&u0.y);
            float2 a1 = __half22float2(*(__half2*)&u1.x);
            float2 b1 = __half22float2(*(__half2*)&u1.y);
            acc0.x += a0.x; acc0.y += a0.y; acc0.z += b0.x; acc0.w += b0.y;
            acc1.x += a1.x; acc1.y += a1.y; acc1.z += b1.x; acc1.w += b1.y;
        }
        if (t < cnt) {
            int j0 = __shfl_sync(0xffffffffu, j, t);
            uint2 u0 = *(const uint2*)(hs + (size_t)j0 * (F1 / 2) + lane * 2);
            float2 a0 = __half22float2(*(__half2*)&u0.x);
            float2 b0 = __half22float2(*(__half2*)&u0.y);
            acc0.x += a0.x; acc0.y += a0.y; acc0.z += b0.x; acc0.w += b0.y;
        }
    }
    float s = dinv_of(i);
    float4 bb = *(const float4*)(b1 + lane * 4);
    float f[4];
    f[0] = fmaxf(fmaf(acc0.x + acc1.x, s, bb.x), 0.f);
    f[1] = fmaxf(fmaf(acc0.y + acc1.y, s, bb.y), 0.f);
    f[2] = fmaxf(fmaf(acc0.z + acc1.z, s, bb.z), 0.f);
    f[3] = fmaxf(fmaf(acc0.w + acc1.w, s, bb.w), 0.f);

    float p[F2];
#pragma unroll
    for (int q = 0; q < F2; q++) {
        float4 w = *(const float4*)(&Wt[q][lane * 4]);
        p[q] = f[0] * w.x + f[1] * w.y + f[2] * w.z + f[3] * w.w;
    }
#pragma unroll
    for (int d = 16; d >= 1; d >>= 1) {
#pragma unroll
        for (int q = 0; q < F2; q++)
            p[q] += __shfl_xor_sync(0xffffffffu, p[q], d);
    }
    if (lane < 4) {
        float4 v = make_float4(p[lane * 4] * s, p[lane * 4 + 1] * s,
                               p[lane * 4 + 2] * s, p[lane * 4 + 3] * s);
        *(float4*)(g_h2 + (size_t)i * F2 + lane * 4) = v;
    }
}

// ---------------- Agg2: 4 threads per node, 16 dims, + b2 -------------------
__global__ void k_agg2(const float* __restrict__ b2, float* __restrict__ out, int n) {
    int gt = blockIdx.x * blockDim.x + threadIdx.x;
    int i = gt >> 2;
    if (i >= n) return;
    int q = (gt & 3) * 4;
    int beg = g_rowptr[i], end = g_rowptr[i + 1];
    const float* hs = g_h2;
    float4 acc = *(const float4*)(hs + (size_t)i * F2 + q);
    for (int e = beg; e < end; e++) {
        int j = g_csr[e];
        float4 v = *(const float4*)(hs + (size_t)j * F2 + q);
        acc.x += v.x; acc.y += v.y; acc.z += v.z; acc.w += v.w;
    }
    float s = dinv_of(i);
    float4 bb = *(const float4*)(b2 + q);
    float4 r = make_float4(fmaf(acc.x, s, bb.x), fmaf(acc.y, s, bb.y),
                           fmaf(acc.z, s, bb.z), fmaf(acc.w, s, bb.w));
    *(float4*)(out + (size_t)i * F2 + q) = r;
}

// ---------------- launch: fork/join graph ------------------------------------
extern "C" void kernel_launch(void* const* d_in, const int* in_sizes, int n_in,
                              void* d_out, int out_size) {
    const float* x  = (const float*)d_in[0];
    const int*   ei = (const int*)d_in[1];
    const float* W1 = (const float*)d_in[2];
    const float* b1 = (const float*)d_in[3];
    const float* W2 = (const float*)d_in[4];
    const float* b2 = (const float*)d_in[5];
    float* out = (float*)d_out;

    int n = in_sizes[0] / F0;       // 100000
    int E = in_sizes[1] / 2;        // 1600000

    static cudaStream_t s2 = 0;
    static cudaEvent_t evFork = 0, evJoin = 0;
    if (!s2) {
        cudaStreamCreateWithFlags(&s2, cudaStreamNonBlocking);
        cudaEventCreateWithFlags(&evFork, cudaEventDisableTiming);
        cudaEventCreateWithFlags(&evJoin, cudaEventDisableTiming);
        cudaFuncSetAttribute(k_gemm1, cudaFuncAttributeMaxDynamicSharedMemorySize,
                             SM_TOTAL);
    }

    int tb = 256;
    k_prepw<<<8, 256>>>(W1);                       // launch 1
    k_zero<<<(n + tb - 1) / tb, tb>>>(n);          // launch 2
    k_deg<<<(E + tb - 1) / tb, tb>>>(ei, E, n);    // launch 3

    cudaEventRecord(evFork, 0);
    cudaStreamWaitEvent(s2, evFork, 0);

    k_gemm1<<<(n + 127) / 128, 256, SM_TOTAL>>>(x, n);   // launch 4 (sampled)

    int nb = (n + 4095) / 4096;
    k_scan1<<<nb, 256, 0, s2>>>(n);
    k_scan2<<<1, 32, 0, s2>>>(nb);
    k_scan3<<<(n + tb - 1) / tb, tb, 0, s2>>>(n, E);
    k_fill<<<(E + tb - 1) / tb, tb, 0, s2>>>(ei, E, n);
    cudaEventRecord(evJoin, s2);

    cudaStreamWaitEvent(0, evJoin, 0);
    k_agg1<<<(n * 32 + tb - 1) / tb, tb>>>(b1, W2, n);
    k_agg2<<<(n * 4 + tb - 1) / tb, tb>>>(b2, out, n);
}